// round 10
// baseline (speedup 1.0000x reference)
#include <cuda_runtime.h>
#include <cuda_fp16.h>
#include <math.h>

#define LL 512
#define DD 256
#define HH 8
#define FIN 1528

#define ACOLS 144                      // packed act cols: 0-135 data, 136-143 zero pad
#define SPITCH 152                     // smem pitch in fp16 (304B row, ldmatrix conflict-free)
#define ROWB 288                       // bytes per packed row (ACOLS*2)
#define CHUNKS 18                      // 16B chunks per row
#define TPX 128                        // out pixels per conv block
#define SROWS (TPX+2)                  // 130 stage rows
#define STAGE_BYTES (SROWS*SPITCH*2)   // 39520
#define BBUF_BYTES (128*SPITCH*2)      // 38912
#define CONV_SMEM (STAGE_BYTES + 2*BBUF_BYTES)   // 117344

// ---------------- scratch (device globals; no allocation allowed) ----------------
__device__ float g_qs[LL*HH*24];
__device__ float g_ks[LL*HH*24];
__device__ float g_vg[LL*HH*24];
__device__ float g_qn[LL*HH];
__device__ float g_kn[LL*HH];
__device__ float g_lg[16*LL*LL];
__device__ float g_ls[LL*HH*LL];
__device__ float g_alpha[LL*HH*LL];
__device__ float g_feat[LL*FIN];
__device__ float g_h1[LL*2*DD];
__device__ __half g_wth[9*128*ACOLS];           // [tap][cout][144] fp16
__device__ __half g_act[(size_t)LL*LL*ACOLS];   // [i][px][144] fp16
__device__ float g_zsum[136], g_zsq[136];
__device__ float g_zmean[136], g_zrstd[136];
__device__ float g_csum[16], g_csq[16];
__device__ float g_cmean[16], g_crstd[16];

__device__ __forceinline__ float lrelu(float v){ return v >= 0.f ? v : 0.01f*v; }

__device__ __forceinline__ void ldsm4(unsigned &r0, unsigned &r1, unsigned &r2, unsigned &r3, unsigned addr){
    asm volatile("ldmatrix.sync.aligned.m8n8.x4.shared.b16 {%0,%1,%2,%3}, [%4];"
        : "=r"(r0),"=r"(r1),"=r"(r2),"=r"(r3) : "r"(addr));
}
__device__ __forceinline__ void mma16816(float* d, unsigned a0, unsigned a1, unsigned a2, unsigned a3,
                                         unsigned b0, unsigned b1){
    asm volatile("mma.sync.aligned.m16n8k16.row.col.f32.f16.f16.f32 "
        "{%0,%1,%2,%3}, {%4,%5,%6,%7}, {%8,%9}, {%0,%1,%2,%3};"
        : "+f"(d[0]),"+f"(d[1]),"+f"(d[2]),"+f"(d[3])
        : "r"(a0),"r"(a1),"r"(a2),"r"(a3),"r"(b0),"r"(b1));
}
__device__ __forceinline__ void cpa16(unsigned dst, const void* src){
    asm volatile("cp.async.cg.shared.global [%0], [%1], 16;" :: "r"(dst), "l"(src));
}
__device__ __forceinline__ void cpa_commit(){ asm volatile("cp.async.commit_group;"); }
__device__ __forceinline__ void cpa_wait1(){ asm volatile("cp.async.wait_group 1;"); }

// ---------------- kernels ----------------
__global__ void k_zero(){
    int tid = threadIdx.x;
    if (tid < 136){ g_zsum[tid]=0.f; g_zsq[tid]=0.f; }
    if (tid < 16){ g_csum[tid]=0.f; g_csq[tid]=0.f; }
}

// cp weights -> fp16, packed layout [tap][cout][144]
__global__ void k_wtrans(const float* __restrict__ cpw){
    int idx = blockIdx.x*256 + threadIdx.x;
    if (idx >= 9*128*ACOLS) return;
    int col = idx % ACOLS;
    int r   = idx / ACOLS;
    int co  = r % 128;
    int tap = r / 128;
    __half out = __float2half(0.f);
    if (col < 136) out = __float2half(cpw[co*1224 + col*9 + tap]);
    g_wth[idx] = out;
}

// q/k/v projection (8 rows per block) + local->global transform + q/k squared norms
__global__ void k_qkv(const float* __restrict__ x, const float* __restrict__ R,
                      const float* __restrict__ t,
                      const float* __restrict__ Wq, const float* __restrict__ Wk,
                      const float* __restrict__ Wv){
    int i0 = blockIdx.x*8, which = blockIdx.y, tid = threadIdx.x; // 192 threads
    const float* W = (which==0)?Wq:((which==1)?Wk:Wv);
    __shared__ float xs[8*256];
    __shared__ float ws[32*192];
    __shared__ float tmp[8*192];
    __shared__ float outp[8*192];
    for (int idx=tid; idx<2048; idx+=192) xs[idx] = x[i0*256 + idx];
    float acc[8];
    #pragma unroll
    for (int r=0;r<8;r++) acc[r]=0.f;
    for (int d0=0; d0<256; d0+=32){
        __syncthreads();
        for (int d=0; d<32; d++) ws[d*192+tid] = W[(d0+d)*192+tid];
        __syncthreads();
        #pragma unroll 8
        for (int d=0; d<32; d++){
            float w = ws[d*192+tid];
            #pragma unroll
            for (int r=0;r<8;r++) acc[r] += xs[r*256+d0+d]*w;
        }
    }
    #pragma unroll
    for (int r=0;r<8;r++) tmp[r*192+tid] = acc[r];
    __syncthreads();
    float* dst = (which==0)?g_qs:((which==1)?g_ks:g_vg);
    for (int idx=tid; idx<512; idx+=192){
        int r = idx>>6, pt = idx&63;
        int i = i0+r;
        float p0=tmp[r*192+pt*3], p1=tmp[r*192+pt*3+1], p2=tmp[r*192+pt*3+2];
        const float* Ri = R + i*9; const float* ti = t + i*3;
        float q0 = Ri[0]*p0+Ri[1]*p1+Ri[2]*p2 + ti[0];
        float q1 = Ri[3]*p0+Ri[4]*p1+Ri[5]*p2 + ti[1];
        float q2 = Ri[6]*p0+Ri[7]*p1+Ri[8]*p2 + ti[2];
        outp[r*192+pt*3]=q0; outp[r*192+pt*3+1]=q1; outp[r*192+pt*3+2]=q2;
        dst[i*192+pt*3]=q0; dst[i*192+pt*3+1]=q1; dst[i*192+pt*3+2]=q2;
    }
    __syncthreads();
    if (which < 2 && tid < 64){
        int r = tid>>3, h = tid&7;
        float s=0.f;
        #pragma unroll
        for (int d=0; d<24; d++){ float v=outp[r*192+h*24+d]; s+=v*v; }
        ((which==0)?g_qn:g_kn)[(i0+r)*8+h]=s;
    }
}

// pair logits: z @ W_p2h -> planes 0..7 of g_lg ; fused z stats + logit channel stats
__global__ void k_pairlogits(const float* __restrict__ z, const float* __restrict__ Wp){
    __shared__ float wpt[8*132];
    __shared__ float zt[32*132];
    __shared__ float ob[32*8];
    __shared__ float rs[256], rs2[256];
    int i = blockIdx.x, tid = threadIdx.x;
    for (int idx=tid; idx<1024; idx+=256){ int p=idx>>3, h=idx&7; wpt[h*132+p]=Wp[idx]; }
    float zs = 0.f, zs2 = 0.f;
    float ls = 0.f, ls2 = 0.f;      // logit stats for this thread's h = tid&7
    for (int jt=0; jt<512; jt+=32){
        __syncthreads();
        for (int idx=tid; idx<4096; idx+=256){
            int j = idx>>7, p = idx&127;
            float v = z[(i*512 + jt + j)*128 + p];
            zt[j*132+p] = v;
            zs += v; zs2 += v*v;
        }
        __syncthreads();
        int jl = tid>>3, h = tid&7;
        float acc = 0.f;
        #pragma unroll
        for (int p4=0; p4<128; p4+=4){
            float4 zv = *(const float4*)&zt[jl*132+p4];
            float4 wv = *(const float4*)&wpt[h*132+p4];
            acc += zv.x*wv.x + zv.y*wv.y + zv.z*wv.z + zv.w*wv.w;
        }
        ob[jl*8+h] = acc;
        ls += acc; ls2 += acc*acc;
        __syncthreads();
        int oc = tid>>5, j2 = tid&31;
        g_lg[oc*262144 + i*512 + jt + j2] = ob[j2*8+oc];
    }
    rs[tid]=zs; rs2[tid]=zs2;
    __syncthreads();
    if (tid < 128){
        atomicAdd(&g_zsum[tid], rs[tid]+rs[tid+128]);
        atomicAdd(&g_zsq[tid],  rs2[tid]+rs2[tid+128]);
    }
    __syncthreads();
    rs[tid]=ls; rs2[tid]=ls2;
    __syncthreads();
    for (int st=128; st>=8; st>>=1){
        if (tid<st){ rs[tid]+=rs[tid+st]; rs2[tid]+=rs2[tid+st]; }
        __syncthreads();
    }
    if (tid < 8){
        atomicAdd(&g_csum[tid], rs[tid]);
        atomicAdd(&g_csq[tid],  rs2[tid]);
    }
}

// spatial logits: planes 8..15 of g_lg (4 i per block); fused logit channel stats
__global__ void k_spatial(const float* __restrict__ gamma){
    int i0 = blockIdx.x*4, tid = threadIdx.x;
    __shared__ float qs[4][200];
    __shared__ float qn_s[32];
    __shared__ float cs[8];
    __shared__ float kt[32*200];
    __shared__ float rs[256], rs2[256];
    for (int idx=tid; idx<4*192; idx+=256){
        int r = idx/192, rr = idx%192;
        int h = rr/24, d = rr%24;
        qs[r][h*25+d] = g_qs[(i0+r)*192+rr];
    }
    if (tid < 32){ int r=tid>>3, h=tid&7; qn_s[tid] = g_qn[(i0+r)*8+h]; }
    if (tid < 8) cs[tid] = -gamma[tid]*sqrtf(2.0f/72.0f)*0.5f;
    float lsum = 0.f, lsum2 = 0.f;
    for (int jt=0; jt<512; jt+=32){
        __syncthreads();
        for (int idx=tid; idx<32*192; idx+=256){
            int j = idx/192, r = idx%192;
            int h = r/24, d = r%24;
            kt[j*200 + h*25 + d] = g_ks[(jt+j)*192 + r];
        }
        __syncthreads();
        int jl = tid>>3, h = tid&7;
        float kn = g_kn[(jt+jl)*8+h];
        #pragma unroll
        for (int r=0; r<4; r++){
            float dot = 0.f;
            #pragma unroll
            for (int d=0; d<24; d++) dot += qs[r][h*25+d]*kt[jl*200+h*25+d];
            float v = (qn_s[r*8+h] + kn - 2.0f*dot)*cs[h];
            g_lg[(8+h)*262144 + (i0+r)*512 + jt + jl] = v;
            lsum += v; lsum2 += v*v;
        }
    }
    rs[tid]=lsum; rs2[tid]=lsum2;
    __syncthreads();
    for (int st=128; st>=8; st>>=1){
        if (tid<st){ rs[tid]+=rs[tid+st]; rs2[tid]+=rs2[tid+st]; }
        __syncthreads();
    }
    if (tid < 8){
        atomicAdd(&g_csum[8+tid], rs[tid]);
        atomicAdd(&g_csq[8+tid],  rs2[tid]);
    }
}

__global__ void k_cfin(){
    int tid = threadIdx.x;
    if (tid < 16){
        float m = g_csum[tid]/262144.0f;
        float var = g_csq[tid]/262144.0f - m*m;
        g_cmean[tid]=m; g_crstd[tid]=rsqrtf(var+1e-5f);
    }
}

// conv ca: inorm(lg) -> 3x3 conv (16->8) -> leaky -> g_ls (i,h,j)
__global__ void k_conv_ca(const float* __restrict__ caw, const float* __restrict__ cab){
    int bid = blockIdx.x;
    int i = bid>>3, jt = (bid&7)<<6;
    int tid = threadIdx.x;
    __shared__ float cw[1152];
    __shared__ float cb[8];
    __shared__ float sg[16*67];
    for (int idx=tid; idx<1152; idx+=256) cw[idx]=caw[idx];
    if (tid<8) cb[tid]=cab[tid];
    int px = tid & 63, g2 = tid >> 6;
    int o0 = g2*2, o1 = o0+1;
    float a0=0.f, a1=0.f;
    for (int di=0; di<3; di++){
        int row = i + di - 1;
        __syncthreads();
        if (row >= 0 && row < 512){
            for (int idx=tid; idx<16*66; idx+=256){
                int c = idx/66, jj = idx%66;
                int col = jt - 1 + jj;
                float v = 0.f;
                if (col>=0 && col<512) v = (g_lg[c*262144 + row*512 + col]-g_cmean[c])*g_crstd[c];
                sg[c*67+jj]=v;
            }
        } else {
            for (int idx=tid; idx<16*67; idx+=256) sg[idx]=0.f;
        }
        __syncthreads();
        for (int dj=0; dj<3; dj++){
            #pragma unroll
            for (int c=0; c<16; c++){
                float a = sg[c*67 + px + dj];
                a0 += a*cw[o0*144 + c*9 + di*3 + dj];
                a1 += a*cw[o1*144 + c*9 + di*3 + dj];
            }
        }
    }
    a0 = lrelu(a0 + cb[o0]);
    a1 = lrelu(a1 + cb[o1]);
    g_ls[i*4096 + o0*512 + jt+px] = a0;
    g_ls[i*4096 + o1*512 + jt+px] = a1;
}

// softmax over j per (i,h); also alpha channel stats
__global__ void k_softmax(){
    int bid = blockIdx.x; int i = bid>>3, h = bid&7;
    int tid = threadIdx.x;
    const float* row = g_ls + i*4096 + h*512;
    float v0 = row[tid], v1 = row[tid+256];
    __shared__ float sh[256];
    sh[tid] = fmaxf(v0,v1); __syncthreads();
    for (int st=128; st>0; st>>=1){ if(tid<st) sh[tid]=fmaxf(sh[tid],sh[tid+st]); __syncthreads(); }
    float mx = sh[0]; __syncthreads();
    float e0 = expf(v0-mx), e1 = expf(v1-mx);
    sh[tid] = e0+e1; __syncthreads();
    for (int st=128; st>0; st>>=1){ if(tid<st) sh[tid]+=sh[tid+st]; __syncthreads(); }
    float inv = 1.0f/sh[0]; __syncthreads();
    float a0 = e0*inv, a1 = e1*inv;
    float* orow = g_alpha + i*4096 + h*512;
    orow[tid]=a0; orow[tid+256]=a1;
    sh[tid]=a0+a1; __syncthreads();
    for (int st=128; st>0; st>>=1){ if(tid<st) sh[tid]+=sh[tid+st]; __syncthreads(); }
    float ssum = sh[0]; __syncthreads();
    sh[tid]=a0*a0+a1*a1; __syncthreads();
    for (int st=128; st>0; st>>=1){ if(tid<st) sh[tid]+=sh[tid+st]; __syncthreads(); }
    if (tid==0){
        atomicAdd(&g_zsum[128+h], ssum);
        atomicAdd(&g_zsq[128+h], sh[0]);
    }
}

__global__ void k_statfin(){
    int tid = threadIdx.x;
    if (tid < 136){
        float cnt = 262144.0f;
        float m = g_zsum[tid]/cnt;
        float var = g_zsq[tid]/cnt - m*m;
        g_zmean[tid]=m; g_zrstd[tid]=rsqrtf(var+1e-5f);
    }
}

// feat_p2n = alpha^T z (per i) FUSED with actprep (normalized fp16 g_act emission)
__global__ void k_featp2n(const float* __restrict__ z){
    int i = blockIdx.x, tid = threadIdx.x;
    __shared__ float al[8*513];
    __shared__ float zt[16*132];
    __shared__ float zm[136], zr[136];
    if (tid < 136){ zm[tid]=g_zmean[tid]; zr[tid]=g_zrstd[tid]; }
    __syncthreads();
    for (int idx=tid; idx<4096; idx+=256){
        int h=idx>>9, j=idx&511;
        float a = g_alpha[i*4096+idx];
        al[h*513+j]=a;
        g_act[((size_t)(i*512)+j)*ACOLS + 128 + h] = __float2half((a - zm[128+h])*zr[128+h]);
    }
    for (int idx=tid; idx<4096; idx+=256){
        int j=idx>>3, c=136+(idx&7);
        g_act[((size_t)(i*512)+j)*ACOLS + c] = __float2half(0.f);
    }
    int h = tid>>5, p4 = (tid&31)*4;
    float acc0=0.f, acc1=0.f, acc2=0.f, acc3=0.f;
    for (int jt=0; jt<512; jt+=16){
        __syncthreads();
        for (int idx=tid; idx<2048; idx+=256){
            int j=idx>>7, p=idx&127;
            float v = z[(i*512+jt+j)*128+p];
            zt[j*132+p]=v;
            g_act[((size_t)(i*512)+jt+j)*ACOLS + p] = __float2half((v - zm[p])*zr[p]);
        }
        __syncthreads();
        #pragma unroll
        for (int j=0; j<16; j++){
            float a = al[h*513 + jt + j];
            const float4 zr4 = *(const float4*)&zt[j*132 + p4];
            acc0 += a*zr4.x; acc1 += a*zr4.y; acc2 += a*zr4.z; acc3 += a*zr4.w;
        }
    }
    float* dst = &g_feat[i*1528 + h*128 + p4];
    dst[0]=acc0; dst[1]=acc1; dst[2]=acc2; dst[3]=acc3;
}

// v & p_CB aggregation + g2l + norms/dirs -> feat_all[1024:1528]
__global__ void k_aggr(const float* __restrict__ R, const float* __restrict__ t,
                       const float* __restrict__ pcb){
    int i = blockIdx.x, tid = threadIdx.x;
    __shared__ float al[8*513];
    __shared__ float ag[216];
    for (int idx=tid; idx<4096; idx+=256){ int h=idx>>9, j=idx&511; al[h*513+j]=g_alpha[i*4096+idx]; }
    __syncthreads();
    if (tid < 192){
        int h = tid/24;
        float s=0.f;
        #pragma unroll 4
        for (int j=0; j<512; j++) s += al[h*513+j]*g_vg[j*192 + tid];
        ag[tid]=s;
    } else if (tid < 216){
        int idx = tid-192; int h = idx/3, c = idx%3;
        float s=0.f;
        #pragma unroll 4
        for (int j=0; j<512; j++) s += al[h*513+j]*pcb[j*3+c];
        ag[tid]=s;
    }
    __syncthreads();
    const float* Ri = R + i*9; const float* ti = t + i*3;
    if (tid < 64){
        float q0=ag[tid*3]-ti[0], q1=ag[tid*3+1]-ti[1], q2=ag[tid*3+2]-ti[2];
        float p0 = Ri[0]*q0+Ri[3]*q1+Ri[6]*q2;
        float p1 = Ri[1]*q0+Ri[4]*q1+Ri[7]*q2;
        float p2 = Ri[2]*q0+Ri[5]*q1+Ri[8]*q2;
        float fn = sqrtf(p0*p0+p1*p1+p2*p2);
        float invn = 1.0f/(fn+1e-6f);
        float* f = &g_feat[i*1528 + 1024];
        f[tid*3]=p0; f[tid*3+1]=p1; f[tid*3+2]=p2;
        f[192+tid]=fn;
        f[256+tid*3]=p0*invn; f[256+tid*3+1]=p1*invn; f[256+tid*3+2]=p2*invn;
    } else if (tid < 72){
        int h = tid-64;
        float q0=ag[192+h*3]-ti[0], q1=ag[192+h*3+1]-ti[1], q2=ag[192+h*3+2]-ti[2];
        float p0 = Ri[0]*q0+Ri[3]*q1+Ri[6]*q2;
        float p1 = Ri[1]*q0+Ri[4]*q1+Ri[7]*q2;
        float p2 = Ri[2]*q0+Ri[5]*q1+Ri[8]*q2;
        float fn = sqrtf(p0*p0+p1*p1+p2*p2);
        float invn = 1.0f/(fn+1e-6f);
        float* f = &g_feat[i*1528 + 1472];
        f[h*3]=p0; f[h*3+1]=p1; f[h*3+2]=p2;
        f[24+h]=fn;
        f[32+h*3]=p0*invn; f[32+h*3+1]=p1*invn; f[32+h*3+2]=p2*invn;
    }
}

// feat_all(512x1528) @ W1(1528x512) + b1 -> g_h1  (grid 32 x 2, 16 rows x 256 cols)
__global__ void k_gemm1(const float* __restrict__ W1, const float* __restrict__ b1){
    int i0 = blockIdx.x*16, n0 = blockIdx.y*256, tid = threadIdx.x;
    __shared__ float fs[128];
    float acc[16];
    #pragma unroll
    for (int r=0;r<16;r++) acc[r]=0.f;
    for (int k0=0; k0<1528; k0+=8){
        __syncthreads();
        if (tid < 128){ int r=tid>>3, kk=tid&7; fs[tid]=g_feat[(i0+r)*1528 + k0 + kk]; }
        __syncthreads();
        #pragma unroll
        for (int kk=0; kk<8; kk++){
            float w = W1[(k0+kk)*512 + n0 + tid];
            #pragma unroll
            for (int r=0; r<16; r++) acc[r] += fs[r*8+kk]*w;
        }
    }
    float bb = b1[n0+tid];
    for (int r=0; r<16; r++) g_h1[(i0+r)*512 + n0 + tid] = acc[r] + bb;
}

// LN over 512 + leaky, in place on g_h1
__global__ void k_ln1(const float* __restrict__ g, const float* __restrict__ b){
    int i = blockIdx.x, tid = threadIdx.x;
    float v0 = g_h1[i*512+tid], v1 = g_h1[i*512+256+tid];
    __shared__ float sh[256];
    sh[tid]=v0+v1; __syncthreads();
    for (int st=128; st>0; st>>=1){ if(tid<st) sh[tid]+=sh[tid+st]; __syncthreads(); }
    float m = sh[0]/512.0f; __syncthreads();
    float d0=v0-m, d1=v1-m;
    sh[tid]=d0*d0+d1*d1; __syncthreads();
    for (int st=128; st>0; st>>=1){ if(tid<st) sh[tid]+=sh[tid+st]; __syncthreads(); }
    float rstd = rsqrtf(sh[0]/512.0f + 1e-5f);
    float y0 = lrelu(d0*rstd*g[tid] + b[tid]);
    float y1 = lrelu(d1*rstd*g[tid+256] + b[tid+256]);
    g_h1[i*512+tid]=y0; g_h1[i*512+256+tid]=y1;
}

// h1 @ W2 + b2, residual, LN -> x_out  (8 rows per block, warp-per-row LN)
__global__ void k_out(const float* __restrict__ x, const float* __restrict__ W2,
                      const float* __restrict__ b2, const float* __restrict__ lng,
                      const float* __restrict__ lnb, float* __restrict__ out){
    int i0 = blockIdx.x*8, tid = threadIdx.x;
    __shared__ float hs[8*512];
    __shared__ float sb[8*256];
    for (int idx=tid; idx<4096; idx+=256) hs[idx] = g_h1[i0*512 + idx];
    __syncthreads();
    float acc[8];
    #pragma unroll
    for (int r=0;r<8;r++) acc[r]=0.f;
    #pragma unroll 4
    for (int k=0; k<512; k++){
        float w = W2[k*256+tid];
        #pragma unroll
        for (int r=0;r<8;r++) acc[r] += hs[r*512+k]*w;
    }
    float bb = b2[tid];
    #pragma unroll
    for (int r=0;r<8;r++) sb[r*256+tid] = acc[r] + bb + x[(i0+r)*256+tid];
    __syncthreads();
    int w = tid>>5, lane = tid&31;
    float v[8];
    float s=0.f, s2=0.f;
    #pragma unroll
    for (int q=0;q<8;q++){
        v[q] = sb[w*256 + q*32 + lane];
        s += v[q]; s2 += v[q]*v[q];
    }
    #pragma unroll
    for (int off=16; off>0; off>>=1){
        s  += __shfl_xor_sync(0xffffffffu, s,  off);
        s2 += __shfl_xor_sync(0xffffffffu, s2, off);
    }
    float m = s/256.0f;
    float rstd = rsqrtf(s2/256.0f - m*m + 1e-5f);
    #pragma unroll
    for (int q=0;q<8;q++){
        int c = q*32 + lane;
        out[(i0+w)*256 + c] = (v[q]-m)*rstd*lng[c] + lnb[c];
    }
}

// pair conv via fp16 mma single-term, 128px x 128cout tile, cp.async double-buffered weights
__global__ void __launch_bounds__(256) k_conv_cp(const float* __restrict__ cpb,
                                                 float* __restrict__ pout){
    extern __shared__ __align__(16) char smem[];
    __half* st = (__half*)smem;                                     // [130][SPITCH]
    unsigned sbase = (unsigned)__cvta_generic_to_shared(st);
    unsigned bbase = sbase + STAGE_BYTES;                           // 2 buffers

    int bid = blockIdx.x;
    int i = bid>>2, jt = (bid&3)<<7;
    int tid = threadIdx.x, lane = tid&31, wid = tid>>5;
    int warp_m = wid>>1, warp_n = wid&1;   // warp_m: 32px, warp_n: 64 cout

    float acc[2][8][4];
    #pragma unroll
    for (int s=0;s<2;s++)
        #pragma unroll
        for (int c=0;c<8;c++){ acc[s][c][0]=0.f; acc[s][c][1]=0.f; acc[s][c][2]=0.f; acc[s][c][3]=0.f; }

    // zero boundary stage rows
    for (int c=tid; c<SPITCH; c+=256){
        st[c] = __float2half(0.f);
        st[(SROWS-1)*SPITCH + c] = __float2half(0.f);
    }

    // prefetch B[0]  (128 rows x 18 chunks of 16B)
    for (int k=tid; k<128*CHUNKS; k+=256){
        int r = k/CHUNKS, ch = k%CHUNKS;
        cpa16(bbase + r*304 + ch*16, (const char*)(g_wth) + (size_t)r*ROWB + ch*16);
    }
    cpa_commit();

    int arow = warp_m*32 + (lane&15);
    unsigned aoff0 = sbase + (unsigned)((arow*SPITCH + ((lane>=16)?8:0))*2);
    int brow = warp_n*64 + (lane&7) + ((lane>=16)?8:0);
    unsigned boff0 = (unsigned)((brow*SPITCH + ((lane&8)?8:0))*2);

    for (int di=0; di<3; di++){
        int row = i + di - 1;
        bool rv = (row>=0 && row<512);
        if (rv){
            const char* srcrow = (const char*)(g_act + ((size_t)row*512)*ACOLS);
            for (int k=tid; k<SROWS*CHUNKS; k+=256){
                int pxl = k/CHUNKS, ch = k%CHUNKS;
                int col = jt - 1 + pxl;
                if (col>=0 && col<512)
                    cpa16(sbase + pxl*304 + ch*16, srcrow + (size_t)col*ROWB + ch*16);
            }
        }
        cpa_commit();
        for (int dj=0; dj<3; dj++){
            int tap = di*3+dj;
            if (tap < 8){
                unsigned dstb = bbase + ((tap+1)&1)*BBUF_BYTES;
                const char* srcb = (const char*)(g_wth + ((size_t)(tap+1)*128)*ACOLS);
                for (int k=tid; k<128*CHUNKS; k+=256){
                    int r = k/CHUNKS, ch = k%CHUNKS;
                    cpa16(dstb + r*304 + ch*16, srcb + (size_t)r*ROWB + ch*16);
                }
            }
            cpa_commit();
            cpa_wait1();
            __syncthreads();
            if (rv){
                unsigned bb = bbase + (tap&1)*BBUF_BYTES + boff0;
                unsigned aoff = aoff0 + (unsigned)(dj*SPITCH*2);
                #pragma unroll
                for (int kc=0; kc<9; kc++){
                    unsigned a0,a1,a2,a3, c0,c1,c2,c3;
                    ldsm4(a0,a1,a2,a3, aoff + (unsigned)((kc*16)*2));
                    ldsm4(c0,c1,c2,c3, aoff + (unsigned)((16*SPITCH + kc*16)*2));
                    #pragma unroll
                    for (int cp=0; cp<4; cp++){
                        unsigned b0,b1,b2,b3;
                        ldsm4(b0,b1,b2,b3, bb + (unsigned)((cp*16*SPITCH + kc*16)*2));
                        mma16816(acc[0][cp*2],   a0,a1,a2,a3, b0,b1);
                        mma16816(acc[0][cp*2+1], a0,a1,a2,a3, b2,b3);
                        mma16816(acc[1][cp*2],   c0,c1,c2,c3, b0,b1);
                        mma16816(acc[1][cp*2+1], c0,c1,c2,c3, b2,b3);
                    }
                }
            }
            __syncthreads();
        }
    }
    // epilogue: bias + leaky relu + store
    int g = lane>>2, tg = lane&3;
    #pragma unroll
    for (int s=0;s<2;s++){
        #pragma unroll
        for (int c8=0; c8<8; c8++){
            int cout = warp_n*64 + c8*8 + tg*2;
            float bb0 = cpb[cout], bb1 = cpb[cout+1];
            int p0 = jt + warp_m*32 + s*16 + g;
            float2 v0, v1;
            v0.x = lrelu(acc[s][c8][0]+bb0); v0.y = lrelu(acc[s][c8][1]+bb1);
            v1.x = lrelu(acc[s][c8][2]+bb0); v1.y = lrelu(acc[s][c8][3]+bb1);
            *(float2*)&pout[(size_t)(i*512 + p0)*128 + cout]     = v0;
            *(float2*)&pout[(size_t)(i*512 + p0 + 8)*128 + cout] = v1;
        }
    }
}

// ---------------- launch ----------------
extern "C" void kernel_launch(void* const* d_in, const int* in_sizes, int n_in,
                              void* d_out, int out_size){
    const float* R    = (const float*)d_in[0];
    const float* t    = (const float*)d_in[1];
    const float* pcb  = (const float*)d_in[2];
    const float* x    = (const float*)d_in[3];
    const float* z    = (const float*)d_in[4];
    const float* Wp   = (const float*)d_in[5];
    const float* gamma= (const float*)d_in[6];
    const float* Wq   = (const float*)d_in[7];
    const float* Wk   = (const float*)d_in[8];
    const float* Wv   = (const float*)d_in[9];
    const float* W1   = (const float*)d_in[10];
    const float* b1   = (const float*)d_in[11];
    const float* ln1g = (const float*)d_in[12];
    const float* ln1b = (const float*)d_in[13];
    const float* W2   = (const float*)d_in[14];
    const float* b2   = (const float*)d_in[15];
    const float* caw  = (const float*)d_in[16];
    const float* cab  = (const float*)d_in[17];
    const float* lng  = (const float*)d_in[18];
    const float* lnb  = (const float*)d_in[19];
    const float* cpw  = (const float*)d_in[20];
    const float* cpb  = (const float*)d_in[21];
    float* out = (float*)d_out;

    static int smem_set = 0;
    if (!smem_set){
        cudaFuncSetAttribute(k_conv_cp, cudaFuncAttributeMaxDynamicSharedMemorySize, CONV_SMEM);
        smem_set = 1;
    }

    k_zero<<<1,256>>>();
    k_wtrans<<<(9*128*ACOLS+255)/256,256>>>(cpw);
    k_qkv<<<dim3(64,3),192>>>(x,R,t,Wq,Wk,Wv);
    k_pairlogits<<<512,256>>>(z,Wp);
    k_spatial<<<128,256>>>(gamma);
    k_cfin<<<1,32>>>();
    k_conv_ca<<<4096,256>>>(caw,cab);
    k_softmax<<<4096,256>>>();
    k_statfin<<<1,256>>>();
    k_featp2n<<<512,256>>>(z);
    k_aggr<<<512,256>>>(R,t,pcb);
    k_gemm1<<<dim3(32,2),256>>>(W1,b1);
    k_ln1<<<512,256>>>(ln1g,ln1b);
    k_out<<<64,256>>>(x,W2,b2,lng,lnb,out);
    k_conv_cp<<<2048,256,CONV_SMEM>>>(cpb, out + 131072);
}

// round 11
// speedup vs baseline: 1.0768x; 1.0768x over previous
#include <cuda_runtime.h>
#include <cuda_fp16.h>
#include <math.h>

#define LL 512
#define DD 256
#define HH 8
#define FIN 1528

#define ACOLS 144                      // packed act cols: 0-135 data, 136-143 zero pad
#define SPITCH 152                     // smem pitch in fp16 (304B row, ldmatrix conflict-free)
#define ROWB 288                       // bytes per packed row (ACOLS*2)
#define CHUNKS 18                      // 16B chunks per row
#define TPX 128                        // out pixels per conv block
#define SROWS (TPX+2)                  // 130 stage rows
#define STAGE_BYTES (SROWS*SPITCH*2)   // 39520
#define BBUF_BYTES (128*SPITCH*2)      // 38912
#define CONV_SMEM (STAGE_BYTES + 2*BBUF_BYTES)   // 117344

// ---------------- scratch (device globals; no allocation allowed) ----------------
__device__ float g_qs[LL*HH*24];
__device__ float g_ks[LL*HH*24];
__device__ float g_vg[LL*HH*24];
__device__ float g_qn[LL*HH];
__device__ float g_kn[LL*HH];
__device__ float g_lg[16*LL*LL];
__device__ float g_ls[LL*HH*LL];
__device__ float g_alpha[LL*HH*LL];
__device__ float g_feat[LL*FIN];
__device__ float g_h1[LL*2*DD];
__device__ __half g_wth[9*128*ACOLS];           // [tap][cout][144] fp16
__device__ __half g_act[(size_t)LL*LL*ACOLS];   // [i][px][144] fp16
__device__ float g_zsum[136], g_zsq[136];
__device__ float g_zmean[136], g_zrstd[136];
__device__ float g_csum[16], g_csq[16];
__device__ float g_cmean[16], g_crstd[16];

__device__ __forceinline__ float lrelu(float v){ return v >= 0.f ? v : 0.01f*v; }

__device__ __forceinline__ void ldsm4(unsigned &r0, unsigned &r1, unsigned &r2, unsigned &r3, unsigned addr){
    asm volatile("ldmatrix.sync.aligned.m8n8.x4.shared.b16 {%0,%1,%2,%3}, [%4];"
        : "=r"(r0),"=r"(r1),"=r"(r2),"=r"(r3) : "r"(addr));
}
__device__ __forceinline__ void mma16816(float* d, unsigned a0, unsigned a1, unsigned a2, unsigned a3,
                                         unsigned b0, unsigned b1){
    asm volatile("mma.sync.aligned.m16n8k16.row.col.f32.f16.f16.f32 "
        "{%0,%1,%2,%3}, {%4,%5,%6,%7}, {%8,%9}, {%0,%1,%2,%3};"
        : "+f"(d[0]),"+f"(d[1]),"+f"(d[2]),"+f"(d[3])
        : "r"(a0),"r"(a1),"r"(a2),"r"(a3),"r"(b0),"r"(b1));
}
__device__ __forceinline__ void cpa16(unsigned dst, const void* src){
    asm volatile("cp.async.cg.shared.global [%0], [%1], 16;" :: "r"(dst), "l"(src));
}
__device__ __forceinline__ void cpa_commit(){ asm volatile("cp.async.commit_group;"); }
__device__ __forceinline__ void cpa_wait1(){ asm volatile("cp.async.wait_group 1;"); }

// ---------------- kernels ----------------
__global__ void k_zero(){
    int tid = threadIdx.x;
    if (tid < 136){ g_zsum[tid]=0.f; g_zsq[tid]=0.f; }
    if (tid < 16){ g_csum[tid]=0.f; g_csq[tid]=0.f; }
}

// cp weights -> fp16, packed layout [tap][cout][144]
__global__ void k_wtrans(const float* __restrict__ cpw){
    int idx = blockIdx.x*256 + threadIdx.x;
    if (idx >= 9*128*ACOLS) return;
    int col = idx % ACOLS;
    int r   = idx / ACOLS;
    int co  = r % 128;
    int tap = r / 128;
    __half out = __float2half(0.f);
    if (col < 136) out = __float2half(cpw[co*1224 + col*9 + tap]);
    g_wth[idx] = out;
}

// q/k/v projection + local->global transform + q/k squared norms (R9 version)
__global__ void k_qkv(const float* __restrict__ x, const float* __restrict__ R,
                      const float* __restrict__ t,
                      const float* __restrict__ Wq, const float* __restrict__ Wk,
                      const float* __restrict__ Wv){
    int i = blockIdx.x, which = blockIdx.y, tid = threadIdx.x; // 192 threads
    const float* W = (which==0)?Wq:((which==1)?Wk:Wv);
    __shared__ float xs[256];
    __shared__ float tmp[192];
    __shared__ float outp[192];
    for (int idx=tid; idx<256; idx+=192) xs[idx] = x[i*256+idx];
    __syncthreads();
    float acc = 0.f;
    #pragma unroll 8
    for (int d=0; d<256; d++) acc += xs[d]*W[d*192+tid];
    tmp[tid] = acc;
    __syncthreads();
    if (tid < 64){
        float p0=tmp[tid*3], p1=tmp[tid*3+1], p2=tmp[tid*3+2];
        const float* Ri = R + i*9; const float* ti = t + i*3;
        float q0 = Ri[0]*p0+Ri[1]*p1+Ri[2]*p2 + ti[0];
        float q1 = Ri[3]*p0+Ri[4]*p1+Ri[5]*p2 + ti[1];
        float q2 = Ri[6]*p0+Ri[7]*p1+Ri[8]*p2 + ti[2];
        outp[tid*3]=q0; outp[tid*3+1]=q1; outp[tid*3+2]=q2;
        float* dst = (which==0)?g_qs:((which==1)?g_ks:g_vg);
        dst[i*192+tid*3]=q0; dst[i*192+tid*3+1]=q1; dst[i*192+tid*3+2]=q2;
    }
    __syncthreads();
    if (which < 2 && tid < 8){
        float s=0.f;
        #pragma unroll
        for (int d=0; d<24; d++){ float v=outp[tid*24+d]; s+=v*v; }
        ((which==0)?g_qn:g_kn)[i*8+tid]=s;
    }
}

// pair logits: z @ W_p2h -> planes 0..7 of g_lg ; fused z stats + logit channel stats
__global__ void k_pairlogits(const float* __restrict__ z, const float* __restrict__ Wp){
    __shared__ float wpt[8*132];
    __shared__ float zt[32*132];
    __shared__ float ob[32*8];
    __shared__ float rs[256], rs2[256];
    int i = blockIdx.x, tid = threadIdx.x;
    for (int idx=tid; idx<1024; idx+=256){ int p=idx>>3, h=idx&7; wpt[h*132+p]=Wp[idx]; }
    float zs = 0.f, zs2 = 0.f;
    float ls = 0.f, ls2 = 0.f;      // logit stats for this thread's h = tid&7
    for (int jt=0; jt<512; jt+=32){
        __syncthreads();
        for (int idx=tid; idx<4096; idx+=256){
            int j = idx>>7, p = idx&127;
            float v = z[(i*512 + jt + j)*128 + p];
            zt[j*132+p] = v;
            zs += v; zs2 += v*v;
        }
        __syncthreads();
        int jl = tid>>3, h = tid&7;
        float acc = 0.f;
        #pragma unroll
        for (int p4=0; p4<128; p4+=4){
            float4 zv = *(const float4*)&zt[jl*132+p4];
            float4 wv = *(const float4*)&wpt[h*132+p4];
            acc += zv.x*wv.x + zv.y*wv.y + zv.z*wv.z + zv.w*wv.w;
        }
        ob[jl*8+h] = acc;
        ls += acc; ls2 += acc*acc;
        __syncthreads();
        int oc = tid>>5, j2 = tid&31;
        g_lg[oc*262144 + i*512 + jt + j2] = ob[j2*8+oc];
    }
    rs[tid]=zs; rs2[tid]=zs2;
    __syncthreads();
    if (tid < 128){
        atomicAdd(&g_zsum[tid], rs[tid]+rs[tid+128]);
        atomicAdd(&g_zsq[tid],  rs2[tid]+rs2[tid+128]);
    }
    __syncthreads();
    rs[tid]=ls; rs2[tid]=ls2;
    __syncthreads();
    for (int st=128; st>=8; st>>=1){
        if (tid<st){ rs[tid]+=rs[tid+st]; rs2[tid]+=rs2[tid+st]; }
        __syncthreads();
    }
    if (tid < 8){
        atomicAdd(&g_csum[tid], rs[tid]);
        atomicAdd(&g_csq[tid],  rs2[tid]);
    }
}

// spatial logits: planes 8..15 of g_lg (4 i per block); fused logit channel stats
__global__ void k_spatial(const float* __restrict__ gamma){
    int i0 = blockIdx.x*4, tid = threadIdx.x;
    __shared__ float qs[4][200];
    __shared__ float qn_s[32];
    __shared__ float cs[8];
    __shared__ float kt[32*200];
    __shared__ float rs[256], rs2[256];
    for (int idx=tid; idx<4*192; idx+=256){
        int r = idx/192, rr = idx%192;
        int h = rr/24, d = rr%24;
        qs[r][h*25+d] = g_qs[(i0+r)*192+rr];
    }
    if (tid < 32){ int r=tid>>3, h=tid&7; qn_s[tid] = g_qn[(i0+r)*8+h]; }
    if (tid < 8) cs[tid] = -gamma[tid]*sqrtf(2.0f/72.0f)*0.5f;
    float lsum = 0.f, lsum2 = 0.f;
    for (int jt=0; jt<512; jt+=32){
        __syncthreads();
        for (int idx=tid; idx<32*192; idx+=256){
            int j = idx/192, r = idx%192;
            int h = r/24, d = r%24;
            kt[j*200 + h*25 + d] = g_ks[(jt+j)*192 + r];
        }
        __syncthreads();
        int jl = tid>>3, h = tid&7;
        float kn = g_kn[(jt+jl)*8+h];
        #pragma unroll
        for (int r=0; r<4; r++){
            float dot = 0.f;
            #pragma unroll
            for (int d=0; d<24; d++) dot += qs[r][h*25+d]*kt[jl*200+h*25+d];
            float v = (qn_s[r*8+h] + kn - 2.0f*dot)*cs[h];
            g_lg[(8+h)*262144 + (i0+r)*512 + jt + jl] = v;
            lsum += v; lsum2 += v*v;
        }
    }
    rs[tid]=lsum; rs2[tid]=lsum2;
    __syncthreads();
    for (int st=128; st>=8; st>>=1){
        if (tid<st){ rs[tid]+=rs[tid+st]; rs2[tid]+=rs2[tid+st]; }
        __syncthreads();
    }
    if (tid < 8){
        atomicAdd(&g_csum[8+tid], rs[tid]);
        atomicAdd(&g_csq[8+tid],  rs2[tid]);
    }
}

__global__ void k_cfin(){
    int tid = threadIdx.x;
    if (tid < 16){
        float m = g_csum[tid]/262144.0f;
        float var = g_csq[tid]/262144.0f - m*m;
        g_cmean[tid]=m; g_crstd[tid]=rsqrtf(var+1e-5f);
    }
}

// conv ca: inorm(lg) -> 3x3 conv (16->8) -> leaky -> g_ls (i,h,j)
__global__ void k_conv_ca(const float* __restrict__ caw, const float* __restrict__ cab){
    int bid = blockIdx.x;
    int i = bid>>3, jt = (bid&7)<<6;
    int tid = threadIdx.x;
    __shared__ float cw[1152];
    __shared__ float cb[8];
    __shared__ float sg[16*67];
    for (int idx=tid; idx<1152; idx+=256) cw[idx]=caw[idx];
    if (tid<8) cb[tid]=cab[tid];
    int px = tid & 63, g2 = tid >> 6;
    int o0 = g2*2, o1 = o0+1;
    float a0=0.f, a1=0.f;
    for (int di=0; di<3; di++){
        int row = i + di - 1;
        __syncthreads();
        if (row >= 0 && row < 512){
            for (int idx=tid; idx<16*66; idx+=256){
                int c = idx/66, jj = idx%66;
                int col = jt - 1 + jj;
                float v = 0.f;
                if (col>=0 && col<512) v = (g_lg[c*262144 + row*512 + col]-g_cmean[c])*g_crstd[c];
                sg[c*67+jj]=v;
            }
        } else {
            for (int idx=tid; idx<16*67; idx+=256) sg[idx]=0.f;
        }
        __syncthreads();
        for (int dj=0; dj<3; dj++){
            #pragma unroll
            for (int c=0; c<16; c++){
                float a = sg[c*67 + px + dj];
                a0 += a*cw[o0*144 + c*9 + di*3 + dj];
                a1 += a*cw[o1*144 + c*9 + di*3 + dj];
            }
        }
    }
    a0 = lrelu(a0 + cb[o0]);
    a1 = lrelu(a1 + cb[o1]);
    g_ls[i*4096 + o0*512 + jt+px] = a0;
    g_ls[i*4096 + o1*512 + jt+px] = a1;
}

// softmax over j per (i,h); also alpha channel stats
__global__ void k_softmax(){
    int bid = blockIdx.x; int i = bid>>3, h = bid&7;
    int tid = threadIdx.x;
    const float* row = g_ls + i*4096 + h*512;
    float v0 = row[tid], v1 = row[tid+256];
    __shared__ float sh[256];
    sh[tid] = fmaxf(v0,v1); __syncthreads();
    for (int st=128; st>0; st>>=1){ if(tid<st) sh[tid]=fmaxf(sh[tid],sh[tid+st]); __syncthreads(); }
    float mx = sh[0]; __syncthreads();
    float e0 = expf(v0-mx), e1 = expf(v1-mx);
    sh[tid] = e0+e1; __syncthreads();
    for (int st=128; st>0; st>>=1){ if(tid<st) sh[tid]+=sh[tid+st]; __syncthreads(); }
    float inv = 1.0f/sh[0]; __syncthreads();
    float a0 = e0*inv, a1 = e1*inv;
    float* orow = g_alpha + i*4096 + h*512;
    orow[tid]=a0; orow[tid+256]=a1;
    sh[tid]=a0+a1; __syncthreads();
    for (int st=128; st>0; st>>=1){ if(tid<st) sh[tid]+=sh[tid+st]; __syncthreads(); }
    float ssum = sh[0]; __syncthreads();
    sh[tid]=a0*a0+a1*a1; __syncthreads();
    for (int st=128; st>0; st>>=1){ if(tid<st) sh[tid]+=sh[tid+st]; __syncthreads(); }
    if (tid==0){
        atomicAdd(&g_zsum[128+h], ssum);
        atomicAdd(&g_zsq[128+h], sh[0]);
    }
}

__global__ void k_statfin(){
    int tid = threadIdx.x;
    if (tid < 136){
        float cnt = 262144.0f;
        float m = g_zsum[tid]/cnt;
        float var = g_zsq[tid]/cnt - m*m;
        g_zmean[tid]=m; g_zrstd[tid]=rsqrtf(var+1e-5f);
    }
}

// feat_p2n = alpha^T z (per i) FUSED with actprep (normalized fp16 g_act emission)
__global__ void k_featp2n(const float* __restrict__ z){
    int i = blockIdx.x, tid = threadIdx.x;
    __shared__ float al[8*513];
    __shared__ float zt[16*132];
    __shared__ float zm[136], zr[136];
    if (tid < 136){ zm[tid]=g_zmean[tid]; zr[tid]=g_zrstd[tid]; }
    __syncthreads();
    for (int idx=tid; idx<4096; idx+=256){
        int h=idx>>9, j=idx&511;
        float a = g_alpha[i*4096+idx];
        al[h*513+j]=a;
        g_act[((size_t)(i*512)+j)*ACOLS + 128 + h] = __float2half((a - zm[128+h])*zr[128+h]);
    }
    for (int idx=tid; idx<4096; idx+=256){
        int j=idx>>3, c=136+(idx&7);
        g_act[((size_t)(i*512)+j)*ACOLS + c] = __float2half(0.f);
    }
    int h = tid>>5, p4 = (tid&31)*4;
    float acc0=0.f, acc1=0.f, acc2=0.f, acc3=0.f;
    for (int jt=0; jt<512; jt+=16){
        __syncthreads();
        for (int idx=tid; idx<2048; idx+=256){
            int j=idx>>7, p=idx&127;
            float v = z[(i*512+jt+j)*128+p];
            zt[j*132+p]=v;
            g_act[((size_t)(i*512)+jt+j)*ACOLS + p] = __float2half((v - zm[p])*zr[p]);
        }
        __syncthreads();
        #pragma unroll
        for (int j=0; j<16; j++){
            float a = al[h*513 + jt + j];
            const float4 zr4 = *(const float4*)&zt[j*132 + p4];
            acc0 += a*zr4.x; acc1 += a*zr4.y; acc2 += a*zr4.z; acc3 += a*zr4.w;
        }
    }
    float* dst = &g_feat[i*1528 + h*128 + p4];
    dst[0]=acc0; dst[1]=acc1; dst[2]=acc2; dst[3]=acc3;
}

// v & p_CB aggregation + g2l + norms/dirs -> feat_all[1024:1528]
__global__ void k_aggr(const float* __restrict__ R, const float* __restrict__ t,
                       const float* __restrict__ pcb){
    int i = blockIdx.x, tid = threadIdx.x;
    __shared__ float al[8*513];
    __shared__ float ag[216];
    for (int idx=tid; idx<4096; idx+=256){ int h=idx>>9, j=idx&511; al[h*513+j]=g_alpha[i*4096+idx]; }
    __syncthreads();
    if (tid < 192){
        int h = tid/24;
        float s=0.f;
        #pragma unroll 4
        for (int j=0; j<512; j++) s += al[h*513+j]*g_vg[j*192 + tid];
        ag[tid]=s;
    } else if (tid < 216){
        int idx = tid-192; int h = idx/3, c = idx%3;
        float s=0.f;
        #pragma unroll 4
        for (int j=0; j<512; j++) s += al[h*513+j]*pcb[j*3+c];
        ag[tid]=s;
    }
    __syncthreads();
    const float* Ri = R + i*9; const float* ti = t + i*3;
    if (tid < 64){
        float q0=ag[tid*3]-ti[0], q1=ag[tid*3+1]-ti[1], q2=ag[tid*3+2]-ti[2];
        float p0 = Ri[0]*q0+Ri[3]*q1+Ri[6]*q2;
        float p1 = Ri[1]*q0+Ri[4]*q1+Ri[7]*q2;
        float p2 = Ri[2]*q0+Ri[5]*q1+Ri[8]*q2;
        float fn = sqrtf(p0*p0+p1*p1+p2*p2);
        float invn = 1.0f/(fn+1e-6f);
        float* f = &g_feat[i*1528 + 1024];
        f[tid*3]=p0; f[tid*3+1]=p1; f[tid*3+2]=p2;
        f[192+tid]=fn;
        f[256+tid*3]=p0*invn; f[256+tid*3+1]=p1*invn; f[256+tid*3+2]=p2*invn;
    } else if (tid < 72){
        int h = tid-64;
        float q0=ag[192+h*3]-ti[0], q1=ag[192+h*3+1]-ti[1], q2=ag[192+h*3+2]-ti[2];
        float p0 = Ri[0]*q0+Ri[3]*q1+Ri[6]*q2;
        float p1 = Ri[1]*q0+Ri[4]*q1+Ri[7]*q2;
        float p2 = Ri[2]*q0+Ri[5]*q1+Ri[8]*q2;
        float fn = sqrtf(p0*p0+p1*p1+p2*p2);
        float invn = 1.0f/(fn+1e-6f);
        float* f = &g_feat[i*1528 + 1472];
        f[h*3]=p0; f[h*3+1]=p1; f[h*3+2]=p2;
        f[24+h]=fn;
        f[32+h*3]=p0*invn; f[32+h*3+1]=p1*invn; f[32+h*3+2]=p2*invn;
    }
}

// feat_all(512x1528) @ W1(1528x512) + b1 -> g_h1  (grid 64 x 2, 8 rows x 256 cols) — R9 version
__global__ void k_gemm1(const float* __restrict__ W1, const float* __restrict__ b1){
    int i0 = blockIdx.x*8, n0 = blockIdx.y*256, tid = threadIdx.x;
    __shared__ float fs[64];
    float acc[8];
    #pragma unroll
    for (int r=0;r<8;r++) acc[r]=0.f;
    for (int k0=0; k0<1528; k0+=8){
        __syncthreads();
        if (tid < 64){ int r=tid>>3, kk=tid&7; fs[tid]=g_feat[(i0+r)*1528 + k0 + kk]; }
        __syncthreads();
        #pragma unroll
        for (int kk=0; kk<8; kk++){
            float w = W1[(k0+kk)*512 + n0 + tid];
            #pragma unroll
            for (int r=0; r<8; r++) acc[r] += fs[r*8+kk]*w;
        }
    }
    float bb = b1[n0+tid];
    for (int r=0; r<8; r++) g_h1[(i0+r)*512 + n0 + tid] = acc[r] + bb;
}

// LN over 512 + leaky, in place on g_h1
__global__ void k_ln1(const float* __restrict__ g, const float* __restrict__ b){
    int i = blockIdx.x, tid = threadIdx.x;
    float v0 = g_h1[i*512+tid], v1 = g_h1[i*512+256+tid];
    __shared__ float sh[256];
    sh[tid]=v0+v1; __syncthreads();
    for (int st=128; st>0; st>>=1){ if(tid<st) sh[tid]+=sh[tid+st]; __syncthreads(); }
    float m = sh[0]/512.0f; __syncthreads();
    float d0=v0-m, d1=v1-m;
    sh[tid]=d0*d0+d1*d1; __syncthreads();
    for (int st=128; st>0; st>>=1){ if(tid<st) sh[tid]+=sh[tid+st]; __syncthreads(); }
    float rstd = rsqrtf(sh[0]/512.0f + 1e-5f);
    float y0 = lrelu(d0*rstd*g[tid] + b[tid]);
    float y1 = lrelu(d1*rstd*g[tid+256] + b[tid+256]);
    g_h1[i*512+tid]=y0; g_h1[i*512+256+tid]=y1;
}

// h1 @ W2 + b2, residual, LN -> x_out  (R9 version: 1 row per block)
__global__ void k_out(const float* __restrict__ x, const float* __restrict__ W2,
                      const float* __restrict__ b2, const float* __restrict__ lng,
                      const float* __restrict__ lnb, float* __restrict__ out){
    int i = blockIdx.x, tid = threadIdx.x;
    __shared__ float hs[512];
    hs[tid]=g_h1[i*512+tid]; hs[tid+256]=g_h1[i*512+256+tid];
    __syncthreads();
    float acc = 0.f;
    #pragma unroll 8
    for (int k=0; k<512; k++) acc += hs[k]*W2[k*256+tid];
    float s = acc + b2[tid] + x[i*256+tid];
    __shared__ float sh[256];
    sh[tid]=s; __syncthreads();
    for (int st=128; st>0; st>>=1){ if(tid<st) sh[tid]+=sh[tid+st]; __syncthreads(); }
    float m = sh[0]/256.0f; __syncthreads();
    float d = s-m;
    sh[tid]=d*d; __syncthreads();
    for (int st=128; st>0; st>>=1){ if(tid<st) sh[tid]+=sh[tid+st]; __syncthreads(); }
    float rstd = rsqrtf(sh[0]/256.0f + 1e-5f);
    out[i*256+tid] = d*rstd*lng[tid] + lnb[tid];
}

// pair conv via fp16 mma single-term, 128px x 128cout tile, cp.async double-buffered weights
__global__ void __launch_bounds__(256) k_conv_cp(const float* __restrict__ cpb,
                                                 float* __restrict__ pout){
    extern __shared__ __align__(16) char smem[];
    __half* st = (__half*)smem;                                     // [130][SPITCH]
    unsigned sbase = (unsigned)__cvta_generic_to_shared(st);
    unsigned bbase = sbase + STAGE_BYTES;                           // 2 buffers

    int bid = blockIdx.x;
    int i = bid>>2, jt = (bid&3)<<7;
    int tid = threadIdx.x, lane = tid&31, wid = tid>>5;
    int warp_m = wid>>1, warp_n = wid&1;   // warp_m: 32px, warp_n: 64 cout

    float acc[2][8][4];
    #pragma unroll
    for (int s=0;s<2;s++)
        #pragma unroll
        for (int c=0;c<8;c++){ acc[s][c][0]=0.f; acc[s][c][1]=0.f; acc[s][c][2]=0.f; acc[s][c][3]=0.f; }

    // zero boundary stage rows
    for (int c=tid; c<SPITCH; c+=256){
        st[c] = __float2half(0.f);
        st[(SROWS-1)*SPITCH + c] = __float2half(0.f);
    }

    // prefetch B[0]  (128 rows x 18 chunks of 16B)
    for (int k=tid; k<128*CHUNKS; k+=256){
        int r = k/CHUNKS, ch = k%CHUNKS;
        cpa16(bbase + r*304 + ch*16, (const char*)(g_wth) + (size_t)r*ROWB + ch*16);
    }
    cpa_commit();

    int arow = warp_m*32 + (lane&15);
    unsigned aoff0 = sbase + (unsigned)((arow*SPITCH + ((lane>=16)?8:0))*2);
    int brow = warp_n*64 + (lane&7) + ((lane>=16)?8:0);
    unsigned boff0 = (unsigned)((brow*SPITCH + ((lane&8)?8:0))*2);

    for (int di=0; di<3; di++){
        int row = i + di - 1;
        bool rv = (row>=0 && row<512);
        if (rv){
            const char* srcrow = (const char*)(g_act + ((size_t)row*512)*ACOLS);
            for (int k=tid; k<SROWS*CHUNKS; k+=256){
                int pxl = k/CHUNKS, ch = k%CHUNKS;
                int col = jt - 1 + pxl;
                if (col>=0 && col<512)
                    cpa16(sbase + pxl*304 + ch*16, srcrow + (size_t)col*ROWB + ch*16);
            }
        }
        cpa_commit();
        for (int dj=0; dj<3; dj++){
            int tap = di*3+dj;
            if (tap < 8){
                unsigned dstb = bbase + ((tap+1)&1)*BBUF_BYTES;
                const char* srcb = (const char*)(g_wth + ((size_t)(tap+1)*128)*ACOLS);
                for (int k=tid; k<128*CHUNKS; k+=256){
                    int r = k/CHUNKS, ch = k%CHUNKS;
                    cpa16(dstb + r*304 + ch*16, srcb + (size_t)r*ROWB + ch*16);
                }
            }
            cpa_commit();
            cpa_wait1();
            __syncthreads();
            if (rv){
                unsigned bb = bbase + (tap&1)*BBUF_BYTES + boff0;
                unsigned aoff = aoff0 + (unsigned)(dj*SPITCH*2);
                #pragma unroll
                for (int kc=0; kc<9; kc++){
                    unsigned a0,a1,a2,a3, c0,c1,c2,c3;
                    ldsm4(a0,a1,a2,a3, aoff + (unsigned)((kc*16)*2));
                    ldsm4(c0,c1,c2,c3, aoff + (unsigned)((16*SPITCH + kc*16)*2));
                    #pragma unroll
                    for (int cp=0; cp<4; cp++){
                        unsigned b0,b1,b2,b3;
                        ldsm4(b0,b1,b2,b3, bb + (unsigned)((cp*16*SPITCH + kc*16)*2));
                        mma16816(acc[0][cp*2],   a0,a1,a2,a3, b0,b1);
                        mma16816(acc[0][cp*2+1], a0,a1,a2,a3, b2,b3);
                        mma16816(acc[1][cp*2],   c0,c1,c2,c3, b0,b1);
                        mma16816(acc[1][cp*2+1], c0,c1,c2,c3, b2,b3);
                    }
                }
            }
            __syncthreads();
        }
    }
    // epilogue: bias + leaky relu + store
    int g = lane>>2, tg = lane&3;
    #pragma unroll
    for (int s=0;s<2;s++){
        #pragma unroll
        for (int c8=0; c8<8; c8++){
            int cout = warp_n*64 + c8*8 + tg*2;
            float bb0 = cpb[cout], bb1 = cpb[cout+1];
            int p0 = jt + warp_m*32 + s*16 + g;
            float2 v0, v1;
            v0.x = lrelu(acc[s][c8][0]+bb0); v0.y = lrelu(acc[s][c8][1]+bb1);
            v1.x = lrelu(acc[s][c8][2]+bb0); v1.y = lrelu(acc[s][c8][3]+bb1);
            *(float2*)&pout[(size_t)(i*512 + p0)*128 + cout]     = v0;
            *(float2*)&pout[(size_t)(i*512 + p0 + 8)*128 + cout] = v1;
        }
    }
}

// ---------------- launch ----------------
extern "C" void kernel_launch(void* const* d_in, const int* in_sizes, int n_in,
                              void* d_out, int out_size){
    const float* R    = (const float*)d_in[0];
    const float* t    = (const float*)d_in[1];
    const float* pcb  = (const float*)d_in[2];
    const float* x    = (const float*)d_in[3];
    const float* z    = (const float*)d_in[4];
    const float* Wp   = (const float*)d_in[5];
    const float* gamma= (const float*)d_in[6];
    const float* Wq   = (const float*)d_in[7];
    const float* Wk   = (const float*)d_in[8];
    const float* Wv   = (const float*)d_in[9];
    const float* W1   = (const float*)d_in[10];
    const float* b1   = (const float*)d_in[11];
    const float* ln1g = (const float*)d_in[12];
    const float* ln1b = (const float*)d_in[13];
    const float* W2   = (const float*)d_in[14];
    const float* b2   = (const float*)d_in[15];
    const float* caw  = (const float*)d_in[16];
    const float* cab  = (const float*)d_in[17];
    const float* lng  = (const float*)d_in[18];
    const float* lnb  = (const float*)d_in[19];
    const float* cpw  = (const float*)d_in[20];
    const float* cpb  = (const float*)d_in[21];
    float* out = (float*)d_out;

    static int smem_set = 0;
    if (!smem_set){
        cudaFuncSetAttribute(k_conv_cp, cudaFuncAttributeMaxDynamicSharedMemorySize, CONV_SMEM);
        smem_set = 1;
    }

    k_zero<<<1,256>>>();
    k_wtrans<<<(9*128*ACOLS+255)/256,256>>>(cpw);
    k_qkv<<<dim3(512,3),192>>>(x,R,t,Wq,Wk,Wv);
    k_pairlogits<<<512,256>>>(z,Wp);
    k_spatial<<<128,256>>>(gamma);
    k_cfin<<<1,32>>>();
    k_conv_ca<<<4096,256>>>(caw,cab);
    k_softmax<<<4096,256>>>();
    k_statfin<<<1,256>>>();
    k_featp2n<<<512,256>>>(z);
    k_aggr<<<512,256>>>(R,t,pcb);
    k_gemm1<<<dim3(64,2),256>>>(W1,b1);
    k_ln1<<<512,256>>>(ln1g,ln1b);
    k_out<<<512,256>>>(x,W2,b2,lng,lnb,out);
    k_conv_cp<<<2048,256,CONV_SMEM>>>(cpb, out + 131072);
}

// round 12
// speedup vs baseline: 1.2600x; 1.1702x over previous
#include <cuda_runtime.h>
#include <cuda_fp16.h>
#include <math.h>

#define LL 512
#define DD 256
#define HH 8
#define FIN 1528

#define ACOLS 144                      // packed act cols: 0-135 data, 136-143 zero pad
#define SPITCH 152                     // smem pitch in fp16 (304B row, ldmatrix conflict-free)
#define ROWB 288                       // bytes per packed row (ACOLS*2)
#define CHUNKS 18                      // 16B chunks per row
#define TPX 128                        // out pixels per conv block
#define SROWS (TPX+2)                  // 130 stage rows
#define STAGE_BYTES (SROWS*SPITCH*2)   // 39520
#define BBUF_BYTES (128*SPITCH*2)      // 38912
#define CONV_SMEM (STAGE_BYTES + 2*BBUF_BYTES)   // 117344

// ---------------- scratch (device globals; no allocation allowed) ----------------
__device__ float g_qs[LL*HH*24];
__device__ float g_ks[LL*HH*24];
__device__ float g_vg[LL*HH*24];
__device__ float g_qn[LL*HH];
__device__ float g_kn[LL*HH];
__device__ float g_lg[16*LL*LL];
__device__ float g_ls[LL*HH*LL];
__device__ float g_alpha[LL*HH*LL];
__device__ float g_feat[LL*FIN];
__device__ float g_h1[LL*2*DD];
__device__ __half g_wth[9*128*ACOLS];           // [tap][cout][144] fp16
__device__ __half g_act[(size_t)LL*LL*ACOLS];   // [i][px][144] fp16
__device__ float g_zsum[136], g_zsq[136];
__device__ float g_zmean[136], g_zrstd[136];
__device__ float g_csum[16], g_csq[16];
__device__ float g_cmean[16], g_crstd[16];

__device__ __forceinline__ float lrelu(float v){ return v >= 0.f ? v : 0.01f*v; }

__device__ __forceinline__ void ldsm4(unsigned &r0, unsigned &r1, unsigned &r2, unsigned &r3, unsigned addr){
    asm volatile("ldmatrix.sync.aligned.m8n8.x4.shared.b16 {%0,%1,%2,%3}, [%4];"
        : "=r"(r0),"=r"(r1),"=r"(r2),"=r"(r3) : "r"(addr));
}
__device__ __forceinline__ void mma16816(float* d, unsigned a0, unsigned a1, unsigned a2, unsigned a3,
                                         unsigned b0, unsigned b1){
    asm volatile("mma.sync.aligned.m16n8k16.row.col.f32.f16.f16.f32 "
        "{%0,%1,%2,%3}, {%4,%5,%6,%7}, {%8,%9}, {%0,%1,%2,%3};"
        : "+f"(d[0]),"+f"(d[1]),"+f"(d[2]),"+f"(d[3])
        : "r"(a0),"r"(a1),"r"(a2),"r"(a3),"r"(b0),"r"(b1));
}
__device__ __forceinline__ void cpa16(unsigned dst, const void* src){
    asm volatile("cp.async.cg.shared.global [%0], [%1], 16;" :: "r"(dst), "l"(src));
}
__device__ __forceinline__ void cpa_commit(){ asm volatile("cp.async.commit_group;"); }
__device__ __forceinline__ void cpa_wait1(){ asm volatile("cp.async.wait_group 1;"); }

// ---------------- kernels ----------------
__global__ void k_zero(){
    int tid = threadIdx.x;
    if (tid < 136){ g_zsum[tid]=0.f; g_zsq[tid]=0.f; }
    if (tid < 16){ g_csum[tid]=0.f; g_csq[tid]=0.f; }
}

// cp weights -> fp16, packed layout [tap][cout][144]
__global__ void k_wtrans(const float* __restrict__ cpw){
    int idx = blockIdx.x*256 + threadIdx.x;
    if (idx >= 9*128*ACOLS) return;
    int col = idx % ACOLS;
    int r   = idx / ACOLS;
    int co  = r % 128;
    int tap = r / 128;
    __half out = __float2half(0.f);
    if (col < 136) out = __float2half(cpw[co*1224 + col*9 + tap]);
    g_wth[idx] = out;
}

// q/k/v projection + local->global transform + q/k squared norms
__global__ void k_qkv(const float* __restrict__ x, const float* __restrict__ R,
                      const float* __restrict__ t,
                      const float* __restrict__ Wq, const float* __restrict__ Wk,
                      const float* __restrict__ Wv){
    int i = blockIdx.x, which = blockIdx.y, tid = threadIdx.x; // 192 threads
    const float* W = (which==0)?Wq:((which==1)?Wk:Wv);
    __shared__ float xs[256];
    __shared__ float tmp[192];
    __shared__ float outp[192];
    for (int idx=tid; idx<256; idx+=192) xs[idx] = x[i*256+idx];
    __syncthreads();
    float acc = 0.f;
    #pragma unroll 8
    for (int d=0; d<256; d++) acc += xs[d]*W[d*192+tid];
    tmp[tid] = acc;
    __syncthreads();
    if (tid < 64){
        float p0=tmp[tid*3], p1=tmp[tid*3+1], p2=tmp[tid*3+2];
        const float* Ri = R + i*9; const float* ti = t + i*3;
        float q0 = Ri[0]*p0+Ri[1]*p1+Ri[2]*p2 + ti[0];
        float q1 = Ri[3]*p0+Ri[4]*p1+Ri[5]*p2 + ti[1];
        float q2 = Ri[6]*p0+Ri[7]*p1+Ri[8]*p2 + ti[2];
        outp[tid*3]=q0; outp[tid*3+1]=q1; outp[tid*3+2]=q2;
        float* dst = (which==0)?g_qs:((which==1)?g_ks:g_vg);
        dst[i*192+tid*3]=q0; dst[i*192+tid*3+1]=q1; dst[i*192+tid*3+2]=q2;
    }
    __syncthreads();
    if (which < 2 && tid < 8){
        float s=0.f;
        #pragma unroll
        for (int d=0; d<24; d++){ float v=outp[tid*24+d]; s+=v*v; }
        ((which==0)?g_qn:g_kn)[i*8+tid]=s;
    }
}

// pair logits: z @ W_p2h -> planes 0..7 of g_lg ; fused z stats + logit channel stats
__global__ void k_pairlogits(const float* __restrict__ z, const float* __restrict__ Wp){
    __shared__ float wpt[8*132];
    __shared__ float zt[32*132];
    __shared__ float ob[32*8];
    __shared__ float rs[256], rs2[256];
    int i = blockIdx.x, tid = threadIdx.x;
    for (int idx=tid; idx<1024; idx+=256){ int p=idx>>3, h=idx&7; wpt[h*132+p]=Wp[idx]; }
    float zs = 0.f, zs2 = 0.f;
    float ls = 0.f, ls2 = 0.f;      // logit stats for this thread's h = tid&7
    for (int jt=0; jt<512; jt+=32){
        __syncthreads();
        for (int idx=tid; idx<4096; idx+=256){
            int j = idx>>7, p = idx&127;
            float v = z[(i*512 + jt + j)*128 + p];
            zt[j*132+p] = v;
            zs += v; zs2 += v*v;
        }
        __syncthreads();
        int jl = tid>>3, h = tid&7;
        float acc = 0.f;
        #pragma unroll
        for (int p4=0; p4<128; p4+=4){
            float4 zv = *(const float4*)&zt[jl*132+p4];
            float4 wv = *(const float4*)&wpt[h*132+p4];
            acc += zv.x*wv.x + zv.y*wv.y + zv.z*wv.z + zv.w*wv.w;
        }
        ob[jl*8+h] = acc;
        ls += acc; ls2 += acc*acc;
        __syncthreads();
        int oc = tid>>5, j2 = tid&31;
        g_lg[oc*262144 + i*512 + jt + j2] = ob[j2*8+oc];
    }
    rs[tid]=zs; rs2[tid]=zs2;
    __syncthreads();
    if (tid < 128){
        atomicAdd(&g_zsum[tid], rs[tid]+rs[tid+128]);
        atomicAdd(&g_zsq[tid],  rs2[tid]+rs2[tid+128]);
    }
    __syncthreads();
    rs[tid]=ls; rs2[tid]=ls2;
    __syncthreads();
    for (int st=128; st>=8; st>>=1){
        if (tid<st){ rs[tid]+=rs[tid+st]; rs2[tid]+=rs2[tid+st]; }
        __syncthreads();
    }
    if (tid < 8){
        atomicAdd(&g_csum[tid], rs[tid]);
        atomicAdd(&g_csq[tid],  rs2[tid]);
    }
}

// spatial logits: planes 8..15 of g_lg (4 i per block); fused logit channel stats
__global__ void k_spatial(const float* __restrict__ gamma){
    int i0 = blockIdx.x*4, tid = threadIdx.x;
    __shared__ float qs[4][200];
    __shared__ float qn_s[32];
    __shared__ float cs[8];
    __shared__ float kt[32*200];
    __shared__ float rs[256], rs2[256];
    for (int idx=tid; idx<4*192; idx+=256){
        int r = idx/192, rr = idx%192;
        int h = rr/24, d = rr%24;
        qs[r][h*25+d] = g_qs[(i0+r)*192+rr];
    }
    if (tid < 32){ int r=tid>>3, h=tid&7; qn_s[tid] = g_qn[(i0+r)*8+h]; }
    if (tid < 8) cs[tid] = -gamma[tid]*sqrtf(2.0f/72.0f)*0.5f;
    float lsum = 0.f, lsum2 = 0.f;
    for (int jt=0; jt<512; jt+=32){
        __syncthreads();
        for (int idx=tid; idx<32*192; idx+=256){
            int j = idx/192, r = idx%192;
            int h = r/24, d = r%24;
            kt[j*200 + h*25 + d] = g_ks[(jt+j)*192 + r];
        }
        __syncthreads();
        int jl = tid>>3, h = tid&7;
        float kn = g_kn[(jt+jl)*8+h];
        #pragma unroll
        for (int r=0; r<4; r++){
            float dot = 0.f;
            #pragma unroll
            for (int d=0; d<24; d++) dot += qs[r][h*25+d]*kt[jl*200+h*25+d];
            float v = (qn_s[r*8+h] + kn - 2.0f*dot)*cs[h];
            g_lg[(8+h)*262144 + (i0+r)*512 + jt + jl] = v;
            lsum += v; lsum2 += v*v;
        }
    }
    rs[tid]=lsum; rs2[tid]=lsum2;
    __syncthreads();
    for (int st=128; st>=8; st>>=1){
        if (tid<st){ rs[tid]+=rs[tid+st]; rs2[tid]+=rs2[tid+st]; }
        __syncthreads();
    }
    if (tid < 8){
        atomicAdd(&g_csum[8+tid], rs[tid]);
        atomicAdd(&g_csq[8+tid],  rs2[tid]);
    }
}

__global__ void k_cfin(){
    int tid = threadIdx.x;
    if (tid < 16){
        float m = g_csum[tid]/262144.0f;
        float var = g_csq[tid]/262144.0f - m*m;
        g_cmean[tid]=m; g_crstd[tid]=rsqrtf(var+1e-5f);
    }
}

// conv ca: inorm(lg) -> 3x3 conv (16->8) -> leaky -> g_ls (i,h,j)
__global__ void k_conv_ca(const float* __restrict__ caw, const float* __restrict__ cab){
    int bid = blockIdx.x;
    int i = bid>>3, jt = (bid&7)<<6;
    int tid = threadIdx.x;
    __shared__ float cw[1152];
    __shared__ float cb[8];
    __shared__ float sg[16*67];
    for (int idx=tid; idx<1152; idx+=256) cw[idx]=caw[idx];
    if (tid<8) cb[tid]=cab[tid];
    int px = tid & 63, g2 = tid >> 6;
    int o0 = g2*2, o1 = o0+1;
    float a0=0.f, a1=0.f;
    for (int di=0; di<3; di++){
        int row = i + di - 1;
        __syncthreads();
        if (row >= 0 && row < 512){
            for (int idx=tid; idx<16*66; idx+=256){
                int c = idx/66, jj = idx%66;
                int col = jt - 1 + jj;
                float v = 0.f;
                if (col>=0 && col<512) v = (g_lg[c*262144 + row*512 + col]-g_cmean[c])*g_crstd[c];
                sg[c*67+jj]=v;
            }
        } else {
            for (int idx=tid; idx<16*67; idx+=256) sg[idx]=0.f;
        }
        __syncthreads();
        for (int dj=0; dj<3; dj++){
            #pragma unroll
            for (int c=0; c<16; c++){
                float a = sg[c*67 + px + dj];
                a0 += a*cw[o0*144 + c*9 + di*3 + dj];
                a1 += a*cw[o1*144 + c*9 + di*3 + dj];
            }
        }
    }
    a0 = lrelu(a0 + cb[o0]);
    a1 = lrelu(a1 + cb[o1]);
    g_ls[i*4096 + o0*512 + jt+px] = a0;
    g_ls[i*4096 + o1*512 + jt+px] = a1;
}

// softmax over j per (i,h); also alpha channel stats
__global__ void k_softmax(){
    int bid = blockIdx.x; int i = bid>>3, h = bid&7;
    int tid = threadIdx.x;
    const float* row = g_ls + i*4096 + h*512;
    float v0 = row[tid], v1 = row[tid+256];
    __shared__ float sh[256];
    sh[tid] = fmaxf(v0,v1); __syncthreads();
    for (int st=128; st>0; st>>=1){ if(tid<st) sh[tid]=fmaxf(sh[tid],sh[tid+st]); __syncthreads(); }
    float mx = sh[0]; __syncthreads();
    float e0 = expf(v0-mx), e1 = expf(v1-mx);
    sh[tid] = e0+e1; __syncthreads();
    for (int st=128; st>0; st>>=1){ if(tid<st) sh[tid]+=sh[tid+st]; __syncthreads(); }
    float inv = 1.0f/sh[0]; __syncthreads();
    float a0 = e0*inv, a1 = e1*inv;
    float* orow = g_alpha + i*4096 + h*512;
    orow[tid]=a0; orow[tid+256]=a1;
    sh[tid]=a0+a1; __syncthreads();
    for (int st=128; st>0; st>>=1){ if(tid<st) sh[tid]+=sh[tid+st]; __syncthreads(); }
    float ssum = sh[0]; __syncthreads();
    sh[tid]=a0*a0+a1*a1; __syncthreads();
    for (int st=128; st>0; st>>=1){ if(tid<st) sh[tid]+=sh[tid+st]; __syncthreads(); }
    if (tid==0){
        atomicAdd(&g_zsum[128+h], ssum);
        atomicAdd(&g_zsq[128+h], sh[0]);
    }
}

__global__ void k_statfin(){
    int tid = threadIdx.x;
    if (tid < 136){
        float cnt = 262144.0f;
        float m = g_zsum[tid]/cnt;
        float var = g_zsq[tid]/cnt - m*m;
        g_zmean[tid]=m; g_zrstd[tid]=rsqrtf(var+1e-5f);
    }
}

// feat_p2n = alpha^T z (per i) FUSED with actprep (normalized fp16 g_act emission)
__global__ void k_featp2n(const float* __restrict__ z){
    int i = blockIdx.x, tid = threadIdx.x;
    __shared__ float al[8*513];
    __shared__ float zt[16*132];
    __shared__ float zm[136], zr[136];
    if (tid < 136){ zm[tid]=g_zmean[tid]; zr[tid]=g_zrstd[tid]; }
    __syncthreads();
    for (int idx=tid; idx<4096; idx+=256){
        int h=idx>>9, j=idx&511;
        float a = g_alpha[i*4096+idx];
        al[h*513+j]=a;
        g_act[((size_t)(i*512)+j)*ACOLS + 128 + h] = __float2half((a - zm[128+h])*zr[128+h]);
    }
    for (int idx=tid; idx<4096; idx+=256){
        int j=idx>>3, c=136+(idx&7);
        g_act[((size_t)(i*512)+j)*ACOLS + c] = __float2half(0.f);
    }
    int h = tid>>5, p4 = (tid&31)*4;
    float acc0=0.f, acc1=0.f, acc2=0.f, acc3=0.f;
    for (int jt=0; jt<512; jt+=16){
        __syncthreads();
        for (int idx=tid; idx<2048; idx+=256){
            int j=idx>>7, p=idx&127;
            float v = z[(i*512+jt+j)*128+p];
            zt[j*132+p]=v;
            g_act[((size_t)(i*512)+jt+j)*ACOLS + p] = __float2half((v - zm[p])*zr[p]);
        }
        __syncthreads();
        #pragma unroll
        for (int j=0; j<16; j++){
            float a = al[h*513 + jt + j];
            const float4 zr4 = *(const float4*)&zt[j*132 + p4];
            acc0 += a*zr4.x; acc1 += a*zr4.y; acc2 += a*zr4.z; acc3 += a*zr4.w;
        }
    }
    float* dst = &g_feat[i*1528 + h*128 + p4];
    dst[0]=acc0; dst[1]=acc1; dst[2]=acc2; dst[3]=acc3;
}

// v & p_CB aggregation + g2l + norms/dirs -> feat_all[1024:1528]
__global__ void k_aggr(const float* __restrict__ R, const float* __restrict__ t,
                       const float* __restrict__ pcb){
    int i = blockIdx.x, tid = threadIdx.x;
    __shared__ float al[8*513];
    __shared__ float ag[216];
    for (int idx=tid; idx<4096; idx+=256){ int h=idx>>9, j=idx&511; al[h*513+j]=g_alpha[i*4096+idx]; }
    __syncthreads();
    if (tid < 192){
        int h = tid/24;
        float s=0.f;
        #pragma unroll 4
        for (int j=0; j<512; j++) s += al[h*513+j]*g_vg[j*192 + tid];
        ag[tid]=s;
    } else if (tid < 216){
        int idx = tid-192; int h = idx/3, c = idx%3;
        float s=0.f;
        #pragma unroll 4
        for (int j=0; j<512; j++) s += al[h*513+j]*pcb[j*3+c];
        ag[tid]=s;
    }
    __syncthreads();
    const float* Ri = R + i*9; const float* ti = t + i*3;
    if (tid < 64){
        float q0=ag[tid*3]-ti[0], q1=ag[tid*3+1]-ti[1], q2=ag[tid*3+2]-ti[2];
        float p0 = Ri[0]*q0+Ri[3]*q1+Ri[6]*q2;
        float p1 = Ri[1]*q0+Ri[4]*q1+Ri[7]*q2;
        float p2 = Ri[2]*q0+Ri[5]*q1+Ri[8]*q2;
        float fn = sqrtf(p0*p0+p1*p1+p2*p2);
        float invn = 1.0f/(fn+1e-6f);
        float* f = &g_feat[i*1528 + 1024];
        f[tid*3]=p0; f[tid*3+1]=p1; f[tid*3+2]=p2;
        f[192+tid]=fn;
        f[256+tid*3]=p0*invn; f[256+tid*3+1]=p1*invn; f[256+tid*3+2]=p2*invn;
    } else if (tid < 72){
        int h = tid-64;
        float q0=ag[192+h*3]-ti[0], q1=ag[192+h*3+1]-ti[1], q2=ag[192+h*3+2]-ti[2];
        float p0 = Ri[0]*q0+Ri[3]*q1+Ri[6]*q2;
        float p1 = Ri[1]*q0+Ri[4]*q1+Ri[7]*q2;
        float p2 = Ri[2]*q0+Ri[5]*q1+Ri[8]*q2;
        float fn = sqrtf(p0*p0+p1*p1+p2*p2);
        float invn = 1.0f/(fn+1e-6f);
        float* f = &g_feat[i*1528 + 1472];
        f[h*3]=p0; f[h*3+1]=p1; f[h*3+2]=p2;
        f[24+h]=fn;
        f[32+h*3]=p0*invn; f[32+h*3+1]=p1*invn; f[32+h*3+2]=p2*invn;
    }
}

// feat_all(512x1528) @ W1(1528x512) + b1 -> g_h1  (grid 64 x 2, 8 rows x 256 cols)
__global__ void k_gemm1(const float* __restrict__ W1, const float* __restrict__ b1){
    int i0 = blockIdx.x*8, n0 = blockIdx.y*256, tid = threadIdx.x;
    __shared__ float fs[64];
    float acc[8];
    #pragma unroll
    for (int r=0;r<8;r++) acc[r]=0.f;
    for (int k0=0; k0<1528; k0+=8){
        __syncthreads();
        if (tid < 64){ int r=tid>>3, kk=tid&7; fs[tid]=g_feat[(i0+r)*1528 + k0 + kk]; }
        __syncthreads();
        #pragma unroll
        for (int kk=0; kk<8; kk++){
            float w = W1[(k0+kk)*512 + n0 + tid];
            #pragma unroll
            for (int r=0; r<8; r++) acc[r] += fs[r*8+kk]*w;
        }
    }
    float bb = b1[n0+tid];
    for (int r=0; r<8; r++) g_h1[(i0+r)*512 + n0 + tid] = acc[r] + bb;
}

// LN over 512 + leaky, in place on g_h1
__global__ void k_ln1(const float* __restrict__ g, const float* __restrict__ b){
    int i = blockIdx.x, tid = threadIdx.x;
    float v0 = g_h1[i*512+tid], v1 = g_h1[i*512+256+tid];
    __shared__ float sh[256];
    sh[tid]=v0+v1; __syncthreads();
    for (int st=128; st>0; st>>=1){ if(tid<st) sh[tid]+=sh[tid+st]; __syncthreads(); }
    float m = sh[0]/512.0f; __syncthreads();
    float d0=v0-m, d1=v1-m;
    sh[tid]=d0*d0+d1*d1; __syncthreads();
    for (int st=128; st>0; st>>=1){ if(tid<st) sh[tid]+=sh[tid+st]; __syncthreads(); }
    float rstd = rsqrtf(sh[0]/512.0f + 1e-5f);
    float y0 = lrelu(d0*rstd*g[tid] + b[tid]);
    float y1 = lrelu(d1*rstd*g[tid+256] + b[tid+256]);
    g_h1[i*512+tid]=y0; g_h1[i*512+256+tid]=y1;
}

// h1 @ W2 + b2, residual, LN -> x_out
__global__ void k_out(const float* __restrict__ x, const float* __restrict__ W2,
                      const float* __restrict__ b2, const float* __restrict__ lng,
                      const float* __restrict__ lnb, float* __restrict__ out){
    int i = blockIdx.x, tid = threadIdx.x;
    __shared__ float hs[512];
    hs[tid]=g_h1[i*512+tid]; hs[tid+256]=g_h1[i*512+256+tid];
    __syncthreads();
    float acc = 0.f;
    #pragma unroll 8
    for (int k=0; k<512; k++) acc += hs[k]*W2[k*256+tid];
    float s = acc + b2[tid] + x[i*256+tid];
    __shared__ float sh[256];
    sh[tid]=s; __syncthreads();
    for (int st=128; st>0; st>>=1){ if(tid<st) sh[tid]+=sh[tid+st]; __syncthreads(); }
    float m = sh[0]/256.0f; __syncthreads();
    float d = s-m;
    sh[tid]=d*d; __syncthreads();
    for (int st=128; st>0; st>>=1){ if(tid<st) sh[tid]+=sh[tid+st]; __syncthreads(); }
    float rstd = rsqrtf(sh[0]/256.0f + 1e-5f);
    out[i*256+tid] = d*rstd*lng[tid] + lnb[tid];
}

// pair conv via fp16 mma single-term, 128px x 128cout tile, cp.async double-buffered weights
__global__ void __launch_bounds__(256) k_conv_cp(const float* __restrict__ cpb,
                                                 float* __restrict__ pout){
    extern __shared__ __align__(16) char smem[];
    __half* st = (__half*)smem;                                     // [130][SPITCH]
    unsigned sbase = (unsigned)__cvta_generic_to_shared(st);
    unsigned bbase = sbase + STAGE_BYTES;                           // 2 buffers

    int bid = blockIdx.x;
    int i = bid>>2, jt = (bid&3)<<7;
    int tid = threadIdx.x, lane = tid&31, wid = tid>>5;
    int warp_m = wid>>1, warp_n = wid&1;   // warp_m: 32px, warp_n: 64 cout

    float acc[2][8][4];
    #pragma unroll
    for (int s=0;s<2;s++)
        #pragma unroll
        for (int c=0;c<8;c++){ acc[s][c][0]=0.f; acc[s][c][1]=0.f; acc[s][c][2]=0.f; acc[s][c][3]=0.f; }

    // zero boundary stage rows
    for (int c=tid; c<SPITCH; c+=256){
        st[c] = __float2half(0.f);
        st[(SROWS-1)*SPITCH + c] = __float2half(0.f);
    }

    // prefetch B[0]  (128 rows x 18 chunks of 16B)
    for (int k=tid; k<128*CHUNKS; k+=256){
        int r = k/CHUNKS, ch = k%CHUNKS;
        cpa16(bbase + r*304 + ch*16, (const char*)(g_wth) + (size_t)r*ROWB + ch*16);
    }
    cpa_commit();

    int arow = warp_m*32 + (lane&15);
    unsigned aoff0 = sbase + (unsigned)((arow*SPITCH + ((lane>=16)?8:0))*2);
    int brow = warp_n*64 + (lane&7) + ((lane>=16)?8:0);
    unsigned boff0 = (unsigned)((brow*SPITCH + ((lane&8)?8:0))*2);

    for (int di=0; di<3; di++){
        int row = i + di - 1;
        bool rv = (row>=0 && row<512);
        if (rv){
            const char* srcrow = (const char*)(g_act + ((size_t)row*512)*ACOLS);
            for (int k=tid; k<SROWS*CHUNKS; k+=256){
                int pxl = k/CHUNKS, ch = k%CHUNKS;
                int col = jt - 1 + pxl;
                if (col>=0 && col<512)
                    cpa16(sbase + pxl*304 + ch*16, srcrow + (size_t)col*ROWB + ch*16);
            }
        }
        cpa_commit();
        for (int dj=0; dj<3; dj++){
            int tap = di*3+dj;
            if (tap < 8){
                unsigned dstb = bbase + ((tap+1)&1)*BBUF_BYTES;
                const char* srcb = (const char*)(g_wth + ((size_t)(tap+1)*128)*ACOLS);
                for (int k=tid; k<128*CHUNKS; k+=256){
                    int r = k/CHUNKS, ch = k%CHUNKS;
                    cpa16(dstb + r*304 + ch*16, srcb + (size_t)r*ROWB + ch*16);
                }
            }
            cpa_commit();
            cpa_wait1();
            __syncthreads();
            if (rv){
                unsigned bb = bbase + (tap&1)*BBUF_BYTES + boff0;
                unsigned aoff = aoff0 + (unsigned)(dj*SPITCH*2);
                #pragma unroll
                for (int kc=0; kc<9; kc++){
                    unsigned a0,a1,a2,a3, c0,c1,c2,c3;
                    ldsm4(a0,a1,a2,a3, aoff + (unsigned)((kc*16)*2));
                    ldsm4(c0,c1,c2,c3, aoff + (unsigned)((16*SPITCH + kc*16)*2));
                    #pragma unroll
                    for (int cp=0; cp<4; cp++){
                        unsigned b0,b1,b2,b3;
                        ldsm4(b0,b1,b2,b3, bb + (unsigned)((cp*16*SPITCH + kc*16)*2));
                        mma16816(acc[0][cp*2],   a0,a1,a2,a3, b0,b1);
                        mma16816(acc[0][cp*2+1], a0,a1,a2,a3, b2,b3);
                        mma16816(acc[1][cp*2],   c0,c1,c2,c3, b0,b1);
                        mma16816(acc[1][cp*2+1], c0,c1,c2,c3, b2,b3);
                    }
                }
            }
            __syncthreads();
        }
    }
    // epilogue: bias + leaky relu + store
    int g = lane>>2, tg = lane&3;
    #pragma unroll
    for (int s=0;s<2;s++){
        #pragma unroll
        for (int c8=0; c8<8; c8++){
            int cout = warp_n*64 + c8*8 + tg*2;
            float bb0 = cpb[cout], bb1 = cpb[cout+1];
            int p0 = jt + warp_m*32 + s*16 + g;
            float2 v0, v1;
            v0.x = lrelu(acc[s][c8][0]+bb0); v0.y = lrelu(acc[s][c8][1]+bb1);
            v1.x = lrelu(acc[s][c8][2]+bb0); v1.y = lrelu(acc[s][c8][3]+bb1);
            *(float2*)&pout[(size_t)(i*512 + p0)*128 + cout]     = v0;
            *(float2*)&pout[(size_t)(i*512 + p0 + 8)*128 + cout] = v1;
        }
    }
}

// ---------------- launch ----------------
extern "C" void kernel_launch(void* const* d_in, const int* in_sizes, int n_in,
                              void* d_out, int out_size){
    const float* R    = (const float*)d_in[0];
    const float* t    = (const float*)d_in[1];
    const float* pcb  = (const float*)d_in[2];
    const float* x    = (const float*)d_in[3];
    const float* z    = (const float*)d_in[4];
    const float* Wp   = (const float*)d_in[5];
    const float* gamma= (const float*)d_in[6];
    const float* Wq   = (const float*)d_in[7];
    const float* Wk   = (const float*)d_in[8];
    const float* Wv   = (const float*)d_in[9];
    const float* W1   = (const float*)d_in[10];
    const float* b1   = (const float*)d_in[11];
    const float* ln1g = (const float*)d_in[12];
    const float* ln1b = (const float*)d_in[13];
    const float* W2   = (const float*)d_in[14];
    const float* b2   = (const float*)d_in[15];
    const float* caw  = (const float*)d_in[16];
    const float* cab  = (const float*)d_in[17];
    const float* lng  = (const float*)d_in[18];
    const float* lnb  = (const float*)d_in[19];
    const float* cpw  = (const float*)d_in[20];
    const float* cpb  = (const float*)d_in[21];
    float* out = (float*)d_out;

    static int initd = 0;
    static cudaStream_t s1;
    static cudaEvent_t e0, e1, e2, e3, e4;
    if (!initd){
        cudaFuncSetAttribute(k_conv_cp, cudaFuncAttributeMaxDynamicSharedMemorySize, CONV_SMEM);
        cudaStreamCreateWithFlags(&s1, cudaStreamNonBlocking);
        cudaEventCreateWithFlags(&e0, cudaEventDisableTiming);
        cudaEventCreateWithFlags(&e1, cudaEventDisableTiming);
        cudaEventCreateWithFlags(&e2, cudaEventDisableTiming);
        cudaEventCreateWithFlags(&e3, cudaEventDisableTiming);
        cudaEventCreateWithFlags(&e4, cudaEventDisableTiming);
        initd = 1;
    }

    // ---- stage 1: zero, then fork { s1: wtrans + pairlogits } ∥ { s0: qkv + spatial }
    k_zero<<<1,256>>>();
    cudaEventRecord(e0, 0);
    cudaStreamWaitEvent(s1, e0, 0);
    k_wtrans<<<(9*128*ACOLS+255)/256,256,0,s1>>>(cpw);
    k_pairlogits<<<512,256,0,s1>>>(z,Wp);
    k_qkv<<<dim3(512,3),192>>>(x,R,t,Wq,Wk,Wv);
    k_spatial<<<128,256>>>(gamma);
    cudaEventRecord(e1, s1);
    cudaStreamWaitEvent(0, e1, 0);

    // ---- stage 2: serial attention midsection on s0
    k_cfin<<<1,32>>>();
    k_conv_ca<<<4096,256>>>(caw,cab);
    k_softmax<<<4096,256>>>();
    k_statfin<<<1,256>>>();

    // ---- stage 3: fork { s1: aggr, then gemm chain after featp2n } ∥ { s0: featp2n + conv_cp }
    cudaEventRecord(e2, 0);
    cudaStreamWaitEvent(s1, e2, 0);
    k_aggr<<<512,256,0,s1>>>(R,t,pcb);
    k_featp2n<<<512,256>>>(z);
    cudaEventRecord(e3, 0);
    cudaStreamWaitEvent(s1, e3, 0);
    k_gemm1<<<dim3(64,2),256,0,s1>>>(W1,b1);
    k_ln1<<<512,256,0,s1>>>(ln1g,ln1b);
    k_out<<<512,256,0,s1>>>(x,W2,b2,lng,lnb,out);
    k_conv_cp<<<2048,256,CONV_SMEM>>>(cpb, out + 131072);

    // ---- join
    cudaEventRecord(e4, s1);
    cudaStreamWaitEvent(0, e4, 0);
}

// round 13
// speedup vs baseline: 1.3370x; 1.0611x over previous
#include <cuda_runtime.h>
#include <cuda_fp16.h>
#include <math.h>

#define LL 512
#define DD 256
#define HH 8
#define FIN 1528

#define ACOLS 144                      // packed act cols: 0-135 data, 136-143 zero pad
#define SPITCH 152                     // smem pitch in fp16 (304B row, ldmatrix conflict-free)
#define ROWB 288                       // bytes per packed row (ACOLS*2)
#define CHUNKS 18                      // 16B chunks per row
#define TPX 128                        // out pixels per conv block
#define SROWS (TPX+2)                  // 130 stage rows
#define STAGE_BYTES (SROWS*SPITCH*2)   // 39520
#define BBUF_BYTES (128*SPITCH*2)      // 38912
#define CONV_SMEM (STAGE_BYTES + 2*BBUF_BYTES)   // 117344

// ---------------- scratch (device globals; no allocation allowed) ----------------
__device__ float g_qs[LL*HH*24];
__device__ float g_ks[LL*HH*24];
__device__ float g_vg[LL*HH*24];
__device__ float g_qn[LL*HH];
__device__ float g_kn[LL*HH];
__device__ float g_lg[16*LL*LL];
__device__ float g_ls[LL*HH*LL];
__device__ float g_alpha[LL*HH*LL];
__device__ float g_feat[LL*FIN];
__device__ float g_h1[LL*2*DD];
__device__ __half g_wth[9*128*ACOLS];           // [tap][cout][144] fp16
__device__ __half g_act[(size_t)LL*LL*ACOLS];   // [i][px][144] fp16
__device__ float g_zsum[136], g_zsq[136];
__device__ float g_zmean[136], g_zrstd[136];
__device__ float g_csum[16], g_csq[16];
__device__ float g_cmean[16], g_crstd[16];

__device__ __forceinline__ float lrelu(float v){ return v >= 0.f ? v : 0.01f*v; }

__device__ __forceinline__ void ldsm4(unsigned &r0, unsigned &r1, unsigned &r2, unsigned &r3, unsigned addr){
    asm volatile("ldmatrix.sync.aligned.m8n8.x4.shared.b16 {%0,%1,%2,%3}, [%4];"
        : "=r"(r0),"=r"(r1),"=r"(r2),"=r"(r3) : "r"(addr));
}
__device__ __forceinline__ void mma16816(float* d, unsigned a0, unsigned a1, unsigned a2, unsigned a3,
                                         unsigned b0, unsigned b1){
    asm volatile("mma.sync.aligned.m16n8k16.row.col.f32.f16.f16.f32 "
        "{%0,%1,%2,%3}, {%4,%5,%6,%7}, {%8,%9}, {%0,%1,%2,%3};"
        : "+f"(d[0]),"+f"(d[1]),"+f"(d[2]),"+f"(d[3])
        : "r"(a0),"r"(a1),"r"(a2),"r"(a3),"r"(b0),"r"(b1));
}
__device__ __forceinline__ void cpa16(unsigned dst, const void* src){
    asm volatile("cp.async.cg.shared.global [%0], [%1], 16;" :: "r"(dst), "l"(src));
}
__device__ __forceinline__ void cpa_commit(){ asm volatile("cp.async.commit_group;"); }
__device__ __forceinline__ void cpa_wait1(){ asm volatile("cp.async.wait_group 1;"); }

// ---------------- kernels ----------------
__global__ void k_zero(){
    int tid = threadIdx.x;
    if (tid < 136){ g_zsum[tid]=0.f; g_zsq[tid]=0.f; }
    if (tid < 16){ g_csum[tid]=0.f; g_csq[tid]=0.f; }
}

// cp weights -> fp16, packed layout [tap][cout][144]
__global__ void k_wtrans(const float* __restrict__ cpw){
    int idx = blockIdx.x*256 + threadIdx.x;
    if (idx >= 9*128*ACOLS) return;
    int col = idx % ACOLS;
    int r   = idx / ACOLS;
    int co  = r % 128;
    int tap = r / 128;
    __half out = __float2half(0.f);
    if (col < 136) out = __float2half(cpw[co*1224 + col*9 + tap]);
    g_wth[idx] = out;
}

// q/k/v projection + local->global transform + q/k squared norms
__global__ void k_qkv(const float* __restrict__ x, const float* __restrict__ R,
                      const float* __restrict__ t,
                      const float* __restrict__ Wq, const float* __restrict__ Wk,
                      const float* __restrict__ Wv){
    int i = blockIdx.x, which = blockIdx.y, tid = threadIdx.x; // 192 threads
    const float* W = (which==0)?Wq:((which==1)?Wk:Wv);
    __shared__ float xs[256];
    __shared__ float tmp[192];
    __shared__ float outp[192];
    for (int idx=tid; idx<256; idx+=192) xs[idx] = x[i*256+idx];
    __syncthreads();
    float acc = 0.f;
    #pragma unroll 8
    for (int d=0; d<256; d++) acc += xs[d]*W[d*192+tid];
    tmp[tid] = acc;
    __syncthreads();
    if (tid < 64){
        float p0=tmp[tid*3], p1=tmp[tid*3+1], p2=tmp[tid*3+2];
        const float* Ri = R + i*9; const float* ti = t + i*3;
        float q0 = Ri[0]*p0+Ri[1]*p1+Ri[2]*p2 + ti[0];
        float q1 = Ri[3]*p0+Ri[4]*p1+Ri[5]*p2 + ti[1];
        float q2 = Ri[6]*p0+Ri[7]*p1+Ri[8]*p2 + ti[2];
        outp[tid*3]=q0; outp[tid*3+1]=q1; outp[tid*3+2]=q2;
        float* dst = (which==0)?g_qs:((which==1)?g_ks:g_vg);
        dst[i*192+tid*3]=q0; dst[i*192+tid*3+1]=q1; dst[i*192+tid*3+2]=q2;
    }
    __syncthreads();
    if (which < 2 && tid < 8){
        float s=0.f;
        #pragma unroll
        for (int d=0; d<24; d++){ float v=outp[tid*24+d]; s+=v*v; }
        ((which==0)?g_qn:g_kn)[i*8+tid]=s;
    }
}

// pair logits: z @ W_p2h -> planes 0..7 of g_lg ; fused z stats + logit channel stats
__global__ void k_pairlogits(const float* __restrict__ z, const float* __restrict__ Wp){
    __shared__ float wpt[8*132];
    __shared__ float zt[32*132];
    __shared__ float ob[32*8];
    __shared__ float rs[256], rs2[256];
    int i = blockIdx.x, tid = threadIdx.x;
    for (int idx=tid; idx<1024; idx+=256){ int p=idx>>3, h=idx&7; wpt[h*132+p]=Wp[idx]; }
    float zs = 0.f, zs2 = 0.f;
    float ls = 0.f, ls2 = 0.f;      // logit stats for this thread's h = tid&7
    for (int jt=0; jt<512; jt+=32){
        __syncthreads();
        for (int idx=tid; idx<4096; idx+=256){
            int j = idx>>7, p = idx&127;
            float v = z[(i*512 + jt + j)*128 + p];
            zt[j*132+p] = v;
            zs += v; zs2 += v*v;
        }
        __syncthreads();
        int jl = tid>>3, h = tid&7;
        float acc = 0.f;
        #pragma unroll
        for (int p4=0; p4<128; p4+=4){
            float4 zv = *(const float4*)&zt[jl*132+p4];
            float4 wv = *(const float4*)&wpt[h*132+p4];
            acc += zv.x*wv.x + zv.y*wv.y + zv.z*wv.z + zv.w*wv.w;
        }
        ob[jl*8+h] = acc;
        ls += acc; ls2 += acc*acc;
        __syncthreads();
        int oc = tid>>5, j2 = tid&31;
        g_lg[oc*262144 + i*512 + jt + j2] = ob[j2*8+oc];
    }
    rs[tid]=zs; rs2[tid]=zs2;
    __syncthreads();
    if (tid < 128){
        atomicAdd(&g_zsum[tid], rs[tid]+rs[tid+128]);
        atomicAdd(&g_zsq[tid],  rs2[tid]+rs2[tid+128]);
    }
    __syncthreads();
    rs[tid]=ls; rs2[tid]=ls2;
    __syncthreads();
    for (int st=128; st>=8; st>>=1){
        if (tid<st){ rs[tid]+=rs[tid+st]; rs2[tid]+=rs2[tid+st]; }
        __syncthreads();
    }
    if (tid < 8){
        atomicAdd(&g_csum[tid], rs[tid]);
        atomicAdd(&g_csq[tid],  rs2[tid]);
    }
}

// spatial logits: planes 8..15 of g_lg (4 i per block); fused logit channel stats
__global__ void k_spatial(const float* __restrict__ gamma){
    int i0 = blockIdx.x*4, tid = threadIdx.x;
    __shared__ float qs[4][200];
    __shared__ float qn_s[32];
    __shared__ float cs[8];
    __shared__ float kt[32*200];
    __shared__ float rs[256], rs2[256];
    for (int idx=tid; idx<4*192; idx+=256){
        int r = idx/192, rr = idx%192;
        int h = rr/24, d = rr%24;
        qs[r][h*25+d] = g_qs[(i0+r)*192+rr];
    }
    if (tid < 32){ int r=tid>>3, h=tid&7; qn_s[tid] = g_qn[(i0+r)*8+h]; }
    if (tid < 8) cs[tid] = -gamma[tid]*sqrtf(2.0f/72.0f)*0.5f;
    float lsum = 0.f, lsum2 = 0.f;
    for (int jt=0; jt<512; jt+=32){
        __syncthreads();
        for (int idx=tid; idx<32*192; idx+=256){
            int j = idx/192, r = idx%192;
            int h = r/24, d = r%24;
            kt[j*200 + h*25 + d] = g_ks[(jt+j)*192 + r];
        }
        __syncthreads();
        int jl = tid>>3, h = tid&7;
        float kn = g_kn[(jt+jl)*8+h];
        #pragma unroll
        for (int r=0; r<4; r++){
            float dot = 0.f;
            #pragma unroll
            for (int d=0; d<24; d++) dot += qs[r][h*25+d]*kt[jl*200+h*25+d];
            float v = (qn_s[r*8+h] + kn - 2.0f*dot)*cs[h];
            g_lg[(8+h)*262144 + (i0+r)*512 + jt + jl] = v;
            lsum += v; lsum2 += v*v;
        }
    }
    rs[tid]=lsum; rs2[tid]=lsum2;
    __syncthreads();
    for (int st=128; st>=8; st>>=1){
        if (tid<st){ rs[tid]+=rs[tid+st]; rs2[tid]+=rs2[tid+st]; }
        __syncthreads();
    }
    if (tid < 8){
        atomicAdd(&g_csum[8+tid], rs[tid]);
        atomicAdd(&g_csq[8+tid],  rs2[tid]);
    }
}

__global__ void k_cfin(){
    int tid = threadIdx.x;
    if (tid < 16){
        float m = g_csum[tid]/262144.0f;
        float var = g_csq[tid]/262144.0f - m*m;
        g_cmean[tid]=m; g_crstd[tid]=rsqrtf(var+1e-5f);
    }
}

// z-channel norm stats (c 0..127): ready right after pairlogits
__global__ void k_statfin_z(){
    int tid = threadIdx.x;
    if (tid < 128){
        float cnt = 262144.0f;
        float m = g_zsum[tid]/cnt;
        float var = g_zsq[tid]/cnt - m*m;
        g_zmean[tid]=m; g_zrstd[tid]=rsqrtf(var+1e-5f);
    }
}

// alpha-channel norm stats (c 128..135): after softmax
__global__ void k_statfin_a(){
    int tid = threadIdx.x;
    if (tid < 8){
        int c = 128+tid;
        float cnt = 262144.0f;
        float m = g_zsum[c]/cnt;
        float var = g_zsq[c]/cnt - m*m;
        g_zmean[c]=m; g_zrstd[c]=rsqrtf(var+1e-5f);
    }
}

// emit normalized z channels of g_act (cols 0-127) + zero pad (136-143); overlaps stage 2
__global__ void k_actprep_z(const float* __restrict__ z){
    int bid = blockIdx.x;
    int i = bid>>3, p0 = (bid&7)<<6;
    int tid = threadIdx.x;
    __shared__ float zm[128], zr[128];
    if (tid < 128){ zm[tid]=g_zmean[tid]; zr[tid]=g_zrstd[tid]; }
    __syncthreads();
    for (int idx=tid; idx<8192; idx+=256){
        int px = idx>>7, c = idx&127;
        float v = (z[((size_t)(i*512) + p0+px)*128 + c] - zm[c])*zr[c];
        g_act[((size_t)(i*512) + p0+px)*ACOLS + c] = __float2half(v);
    }
    for (int idx=tid; idx<512; idx+=256){
        int px = idx>>3, c = 136+(idx&7);
        g_act[((size_t)(i*512) + p0+px)*ACOLS + c] = __float2half(0.f);
    }
}

// conv ca: inorm(lg) -> 3x3 conv (16->8) -> leaky -> g_ls (i,h,j)
__global__ void k_conv_ca(const float* __restrict__ caw, const float* __restrict__ cab){
    int bid = blockIdx.x;
    int i = bid>>3, jt = (bid&7)<<6;
    int tid = threadIdx.x;
    __shared__ float cw[1152];
    __shared__ float cb[8];
    __shared__ float sg[16*67];
    for (int idx=tid; idx<1152; idx+=256) cw[idx]=caw[idx];
    if (tid<8) cb[tid]=cab[tid];
    int px = tid & 63, g2 = tid >> 6;
    int o0 = g2*2, o1 = o0+1;
    float a0=0.f, a1=0.f;
    for (int di=0; di<3; di++){
        int row = i + di - 1;
        __syncthreads();
        if (row >= 0 && row < 512){
            for (int idx=tid; idx<16*66; idx+=256){
                int c = idx/66, jj = idx%66;
                int col = jt - 1 + jj;
                float v = 0.f;
                if (col>=0 && col<512) v = (g_lg[c*262144 + row*512 + col]-g_cmean[c])*g_crstd[c];
                sg[c*67+jj]=v;
            }
        } else {
            for (int idx=tid; idx<16*67; idx+=256) sg[idx]=0.f;
        }
        __syncthreads();
        for (int dj=0; dj<3; dj++){
            #pragma unroll
            for (int c=0; c<16; c++){
                float a = sg[c*67 + px + dj];
                a0 += a*cw[o0*144 + c*9 + di*3 + dj];
                a1 += a*cw[o1*144 + c*9 + di*3 + dj];
            }
        }
    }
    a0 = lrelu(a0 + cb[o0]);
    a1 = lrelu(a1 + cb[o1]);
    g_ls[i*4096 + o0*512 + jt+px] = a0;
    g_ls[i*4096 + o1*512 + jt+px] = a1;
}

// softmax over j per (i,h); also alpha channel stats
__global__ void k_softmax(){
    int bid = blockIdx.x; int i = bid>>3, h = bid&7;
    int tid = threadIdx.x;
    const float* row = g_ls + i*4096 + h*512;
    float v0 = row[tid], v1 = row[tid+256];
    __shared__ float sh[256];
    sh[tid] = fmaxf(v0,v1); __syncthreads();
    for (int st=128; st>0; st>>=1){ if(tid<st) sh[tid]=fmaxf(sh[tid],sh[tid+st]); __syncthreads(); }
    float mx = sh[0]; __syncthreads();
    float e0 = expf(v0-mx), e1 = expf(v1-mx);
    sh[tid] = e0+e1; __syncthreads();
    for (int st=128; st>0; st>>=1){ if(tid<st) sh[tid]+=sh[tid+st]; __syncthreads(); }
    float inv = 1.0f/sh[0]; __syncthreads();
    float a0 = e0*inv, a1 = e1*inv;
    float* orow = g_alpha + i*4096 + h*512;
    orow[tid]=a0; orow[tid+256]=a1;
    sh[tid]=a0+a1; __syncthreads();
    for (int st=128; st>0; st>>=1){ if(tid<st) sh[tid]+=sh[tid+st]; __syncthreads(); }
    float ssum = sh[0]; __syncthreads();
    sh[tid]=a0*a0+a1*a1; __syncthreads();
    for (int st=128; st>0; st>>=1){ if(tid<st) sh[tid]+=sh[tid+st]; __syncthreads(); }
    if (tid==0){
        atomicAdd(&g_zsum[128+h], ssum);
        atomicAdd(&g_zsq[128+h], sh[0]);
    }
}

// feat_p2n = alpha^T z (per i) ; also emits alpha-channel g_act cols (128-135)
__global__ void k_featp2n(const float* __restrict__ z){
    int i = blockIdx.x, tid = threadIdx.x;
    __shared__ float al[8*513];
    __shared__ float zt[16*132];
    __shared__ float am[8], ar[8];
    if (tid < 8){ am[tid]=g_zmean[128+tid]; ar[tid]=g_zrstd[128+tid]; }
    __syncthreads();
    for (int idx=tid; idx<4096; idx+=256){
        int h=idx>>9, j=idx&511;
        float a = g_alpha[i*4096+idx];
        al[h*513+j]=a;
        g_act[((size_t)(i*512)+j)*ACOLS + 128 + h] = __float2half((a - am[h])*ar[h]);
    }
    int h = tid>>5, p4 = (tid&31)*4;
    float acc0=0.f, acc1=0.f, acc2=0.f, acc3=0.f;
    for (int jt=0; jt<512; jt+=16){
        __syncthreads();
        for (int idx=tid; idx<2048; idx+=256){
            int j=idx>>7, p=idx&127;
            zt[j*132+p]=z[(i*512+jt+j)*128+p];
        }
        __syncthreads();
        #pragma unroll
        for (int j=0; j<16; j++){
            float a = al[h*513 + jt + j];
            const float4 zr4 = *(const float4*)&zt[j*132 + p4];
            acc0 += a*zr4.x; acc1 += a*zr4.y; acc2 += a*zr4.z; acc3 += a*zr4.w;
        }
    }
    float* dst = &g_feat[i*1528 + h*128 + p4];
    dst[0]=acc0; dst[1]=acc1; dst[2]=acc2; dst[3]=acc3;
}

// v & p_CB aggregation + g2l + norms/dirs -> feat_all[1024:1528]
__global__ void k_aggr(const float* __restrict__ R, const float* __restrict__ t,
                       const float* __restrict__ pcb){
    int i = blockIdx.x, tid = threadIdx.x;
    __shared__ float al[8*513];
    __shared__ float ag[216];
    for (int idx=tid; idx<4096; idx+=256){ int h=idx>>9, j=idx&511; al[h*513+j]=g_alpha[i*4096+idx]; }
    __syncthreads();
    if (tid < 192){
        int h = tid/24;
        float s=0.f;
        #pragma unroll 4
        for (int j=0; j<512; j++) s += al[h*513+j]*g_vg[j*192 + tid];
        ag[tid]=s;
    } else if (tid < 216){
        int idx = tid-192; int h = idx/3, c = idx%3;
        float s=0.f;
        #pragma unroll 4
        for (int j=0; j<512; j++) s += al[h*513+j]*pcb[j*3+c];
        ag[tid]=s;
    }
    __syncthreads();
    const float* Ri = R + i*9; const float* ti = t + i*3;
    if (tid < 64){
        float q0=ag[tid*3]-ti[0], q1=ag[tid*3+1]-ti[1], q2=ag[tid*3+2]-ti[2];
        float p0 = Ri[0]*q0+Ri[3]*q1+Ri[6]*q2;
        float p1 = Ri[1]*q0+Ri[4]*q1+Ri[7]*q2;
        float p2 = Ri[2]*q0+Ri[5]*q1+Ri[8]*q2;
        float fn = sqrtf(p0*p0+p1*p1+p2*p2);
        float invn = 1.0f/(fn+1e-6f);
        float* f = &g_feat[i*1528 + 1024];
        f[tid*3]=p0; f[tid*3+1]=p1; f[tid*3+2]=p2;
        f[192+tid]=fn;
        f[256+tid*3]=p0*invn; f[256+tid*3+1]=p1*invn; f[256+tid*3+2]=p2*invn;
    } else if (tid < 72){
        int h = tid-64;
        float q0=ag[192+h*3]-ti[0], q1=ag[192+h*3+1]-ti[1], q2=ag[192+h*3+2]-ti[2];
        float p0 = Ri[0]*q0+Ri[3]*q1+Ri[6]*q2;
        float p1 = Ri[1]*q0+Ri[4]*q1+Ri[7]*q2;
        float p2 = Ri[2]*q0+Ri[5]*q1+Ri[8]*q2;
        float fn = sqrtf(p0*p0+p1*p1+p2*p2);
        float invn = 1.0f/(fn+1e-6f);
        float* f = &g_feat[i*1528 + 1472];
        f[h*3]=p0; f[h*3+1]=p1; f[h*3+2]=p2;
        f[24+h]=fn;
        f[32+h*3]=p0*invn; f[32+h*3+1]=p1*invn; f[32+h*3+2]=p2*invn;
    }
}

// feat_all(512x1528) @ W1(1528x512) + b1 -> g_h1  (grid 64 x 2, 8 rows x 256 cols)
__global__ void k_gemm1(const float* __restrict__ W1, const float* __restrict__ b1){
    int i0 = blockIdx.x*8, n0 = blockIdx.y*256, tid = threadIdx.x;
    __shared__ float fs[64];
    float acc[8];
    #pragma unroll
    for (int r=0;r<8;r++) acc[r]=0.f;
    for (int k0=0; k0<1528; k0+=8){
        __syncthreads();
        if (tid < 64){ int r=tid>>3, kk=tid&7; fs[tid]=g_feat[(i0+r)*1528 + k0 + kk]; }
        __syncthreads();
        #pragma unroll
        for (int kk=0; kk<8; kk++){
            float w = W1[(k0+kk)*512 + n0 + tid];
            #pragma unroll
            for (int r=0; r<8; r++) acc[r] += fs[r*8+kk]*w;
        }
    }
    float bb = b1[n0+tid];
    for (int r=0; r<8; r++) g_h1[(i0+r)*512 + n0 + tid] = acc[r] + bb;
}

// LN over 512 + leaky, in place on g_h1
__global__ void k_ln1(const float* __restrict__ g, const float* __restrict__ b){
    int i = blockIdx.x, tid = threadIdx.x;
    float v0 = g_h1[i*512+tid], v1 = g_h1[i*512+256+tid];
    __shared__ float sh[256];
    sh[tid]=v0+v1; __syncthreads();
    for (int st=128; st>0; st>>=1){ if(tid<st) sh[tid]+=sh[tid+st]; __syncthreads(); }
    float m = sh[0]/512.0f; __syncthreads();
    float d0=v0-m, d1=v1-m;
    sh[tid]=d0*d0+d1*d1; __syncthreads();
    for (int st=128; st>0; st>>=1){ if(tid<st) sh[tid]+=sh[tid+st]; __syncthreads(); }
    float rstd = rsqrtf(sh[0]/512.0f + 1e-5f);
    float y0 = lrelu(d0*rstd*g[tid] + b[tid]);
    float y1 = lrelu(d1*rstd*g[tid+256] + b[tid+256]);
    g_h1[i*512+tid]=y0; g_h1[i*512+256+tid]=y1;
}

// h1 @ W2 + b2, residual, LN -> x_out
__global__ void k_out(const float* __restrict__ x, const float* __restrict__ W2,
                      const float* __restrict__ b2, const float* __restrict__ lng,
                      const float* __restrict__ lnb, float* __restrict__ out){
    int i = blockIdx.x, tid = threadIdx.x;
    __shared__ float hs[512];
    hs[tid]=g_h1[i*512+tid]; hs[tid+256]=g_h1[i*512+256+tid];
    __syncthreads();
    float acc = 0.f;
    #pragma unroll 8
    for (int k=0; k<512; k++) acc += hs[k]*W2[k*256+tid];
    float s = acc + b2[tid] + x[i*256+tid];
    __shared__ float sh[256];
    sh[tid]=s; __syncthreads();
    for (int st=128; st>0; st>>=1){ if(tid<st) sh[tid]+=sh[tid+st]; __syncthreads(); }
    float m = sh[0]/256.0f; __syncthreads();
    float d = s-m;
    sh[tid]=d*d; __syncthreads();
    for (int st=128; st>0; st>>=1){ if(tid<st) sh[tid]+=sh[tid+st]; __syncthreads(); }
    float rstd = rsqrtf(sh[0]/256.0f + 1e-5f);
    out[i*256+tid] = d*rstd*lng[tid] + lnb[tid];
}

// pair conv via fp16 mma single-term, 128px x 128cout tile, cp.async double-buffered weights
__global__ void __launch_bounds__(256) k_conv_cp(const float* __restrict__ cpb,
                                                 float* __restrict__ pout){
    extern __shared__ __align__(16) char smem[];
    __half* st = (__half*)smem;                                     // [130][SPITCH]
    unsigned sbase = (unsigned)__cvta_generic_to_shared(st);
    unsigned bbase = sbase + STAGE_BYTES;                           // 2 buffers

    int bid = blockIdx.x;
    int i = bid>>2, jt = (bid&3)<<7;
    int tid = threadIdx.x, lane = tid&31, wid = tid>>5;
    int warp_m = wid>>1, warp_n = wid&1;   // warp_m: 32px, warp_n: 64 cout

    float acc[2][8][4];
    #pragma unroll
    for (int s=0;s<2;s++)
        #pragma unroll
        for (int c=0;c<8;c++){ acc[s][c][0]=0.f; acc[s][c][1]=0.f; acc[s][c][2]=0.f; acc[s][c][3]=0.f; }

    // zero boundary stage rows
    for (int c=tid; c<SPITCH; c+=256){
        st[c] = __float2half(0.f);
        st[(SROWS-1)*SPITCH + c] = __float2half(0.f);
    }

    // prefetch B[0]  (128 rows x 18 chunks of 16B)
    for (int k=tid; k<128*CHUNKS; k+=256){
        int r = k/CHUNKS, ch = k%CHUNKS;
        cpa16(bbase + r*304 + ch*16, (const char*)(g_wth) + (size_t)r*ROWB + ch*16);
    }
    cpa_commit();

    int arow = warp_m*32 + (lane&15);
    unsigned aoff0 = sbase + (unsigned)((arow*SPITCH + ((lane>=16)?8:0))*2);
    int brow = warp_n*64 + (lane&7) + ((lane>=16)?8:0);
    unsigned boff0 = (unsigned)((brow*SPITCH + ((lane&8)?8:0))*2);

    for (int di=0; di<3; di++){
        int row = i + di - 1;
        bool rv = (row>=0 && row<512);
        if (rv){
            const char* srcrow = (const char*)(g_act + ((size_t)row*512)*ACOLS);
            for (int k=tid; k<SROWS*CHUNKS; k+=256){
                int pxl = k/CHUNKS, ch = k%CHUNKS;
                int col = jt - 1 + pxl;
                if (col>=0 && col<512)
                    cpa16(sbase + pxl*304 + ch*16, srcrow + (size_t)col*ROWB + ch*16);
            }
        }
        cpa_commit();
        for (int dj=0; dj<3; dj++){
            int tap = di*3+dj;
            if (tap < 8){
                unsigned dstb = bbase + ((tap+1)&1)*BBUF_BYTES;
                const char* srcb = (const char*)(g_wth + ((size_t)(tap+1)*128)*ACOLS);
                for (int k=tid; k<128*CHUNKS; k+=256){
                    int r = k/CHUNKS, ch = k%CHUNKS;
                    cpa16(dstb + r*304 + ch*16, srcb + (size_t)r*ROWB + ch*16);
                }
            }
            cpa_commit();
            cpa_wait1();
            __syncthreads();
            if (rv){
                unsigned bb = bbase + (tap&1)*BBUF_BYTES + boff0;
                unsigned aoff = aoff0 + (unsigned)(dj*SPITCH*2);
                #pragma unroll
                for (int kc=0; kc<9; kc++){
                    unsigned a0,a1,a2,a3, c0,c1,c2,c3;
                    ldsm4(a0,a1,a2,a3, aoff + (unsigned)((kc*16)*2));
                    ldsm4(c0,c1,c2,c3, aoff + (unsigned)((16*SPITCH + kc*16)*2));
                    #pragma unroll
                    for (int cp=0; cp<4; cp++){
                        unsigned b0,b1,b2,b3;
                        ldsm4(b0,b1,b2,b3, bb + (unsigned)((cp*16*SPITCH + kc*16)*2));
                        mma16816(acc[0][cp*2],   a0,a1,a2,a3, b0,b1);
                        mma16816(acc[0][cp*2+1], a0,a1,a2,a3, b2,b3);
                        mma16816(acc[1][cp*2],   c0,c1,c2,c3, b0,b1);
                        mma16816(acc[1][cp*2+1], c0,c1,c2,c3, b2,b3);
                    }
                }
            }
            __syncthreads();
        }
    }
    // epilogue: bias + leaky relu + store
    int g = lane>>2, tg = lane&3;
    #pragma unroll
    for (int s=0;s<2;s++){
        #pragma unroll
        for (int c8=0; c8<8; c8++){
            int cout = warp_n*64 + c8*8 + tg*2;
            float bb0 = cpb[cout], bb1 = cpb[cout+1];
            int p0 = jt + warp_m*32 + s*16 + g;
            float2 v0, v1;
            v0.x = lrelu(acc[s][c8][0]+bb0); v0.y = lrelu(acc[s][c8][1]+bb1);
            v1.x = lrelu(acc[s][c8][2]+bb0); v1.y = lrelu(acc[s][c8][3]+bb1);
            *(float2*)&pout[(size_t)(i*512 + p0)*128 + cout]     = v0;
            *(float2*)&pout[(size_t)(i*512 + p0 + 8)*128 + cout] = v1;
        }
    }
}

// ---------------- launch ----------------
extern "C" void kernel_launch(void* const* d_in, const int* in_sizes, int n_in,
                              void* d_out, int out_size){
    const float* R    = (const float*)d_in[0];
    const float* t    = (const float*)d_in[1];
    const float* pcb  = (const float*)d_in[2];
    const float* x    = (const float*)d_in[3];
    const float* z    = (const float*)d_in[4];
    const float* Wp   = (const float*)d_in[5];
    const float* gamma= (const float*)d_in[6];
    const float* Wq   = (const float*)d_in[7];
    const float* Wk   = (const float*)d_in[8];
    const float* Wv   = (const float*)d_in[9];
    const float* W1   = (const float*)d_in[10];
    const float* b1   = (const float*)d_in[11];
    const float* ln1g = (const float*)d_in[12];
    const float* ln1b = (const float*)d_in[13];
    const float* W2   = (const float*)d_in[14];
    const float* b2   = (const float*)d_in[15];
    const float* caw  = (const float*)d_in[16];
    const float* cab  = (const float*)d_in[17];
    const float* lng  = (const float*)d_in[18];
    const float* lnb  = (const float*)d_in[19];
    const float* cpw  = (const float*)d_in[20];
    const float* cpb  = (const float*)d_in[21];
    float* out = (float*)d_out;

    static int initd = 0;
    static cudaStream_t s1;
    static cudaEvent_t e0, e1, e2, e3, e4, e5;
    if (!initd){
        cudaFuncSetAttribute(k_conv_cp, cudaFuncAttributeMaxDynamicSharedMemorySize, CONV_SMEM);
        cudaStreamCreateWithFlags(&s1, cudaStreamNonBlocking);
        cudaEventCreateWithFlags(&e0, cudaEventDisableTiming);
        cudaEventCreateWithFlags(&e1, cudaEventDisableTiming);
        cudaEventCreateWithFlags(&e2, cudaEventDisableTiming);
        cudaEventCreateWithFlags(&e3, cudaEventDisableTiming);
        cudaEventCreateWithFlags(&e4, cudaEventDisableTiming);
        cudaEventCreateWithFlags(&e5, cudaEventDisableTiming);
        initd = 1;
    }

    // ---- stage 1: zero, fork { s1: wtrans + pairlogits + statfin_z + actprep_z } ∥ { s0: qkv + spatial }
    k_zero<<<1,256>>>();
    cudaEventRecord(e0, 0);
    cudaStreamWaitEvent(s1, e0, 0);
    k_wtrans<<<(9*128*ACOLS+255)/256,256,0,s1>>>(cpw);
    k_pairlogits<<<512,256,0,s1>>>(z,Wp);
    cudaEventRecord(e1, s1);                 // pairlogits done (csum h0-7, zsum 0-127)
    k_statfin_z<<<1,128,0,s1>>>();
    k_actprep_z<<<4096,256,0,s1>>>(z);       // overlaps stage 2 on s0
    cudaEventRecord(e5, s1);                 // g_act z-channels ready
    k_qkv<<<dim3(512,3),192>>>(x,R,t,Wq,Wk,Wv);
    k_spatial<<<128,256>>>(gamma);
    cudaStreamWaitEvent(0, e1, 0);

    // ---- stage 2: serial attention midsection on s0
    k_cfin<<<1,32>>>();
    k_conv_ca<<<4096,256>>>(caw,cab);
    k_softmax<<<4096,256>>>();
    k_statfin_a<<<1,32>>>();

    // ---- stage 3: fork { s1: aggr, gemm chain } ∥ { s0: featp2n + conv_cp }
    cudaEventRecord(e2, 0);
    cudaStreamWaitEvent(s1, e2, 0);
    k_aggr<<<512,256,0,s1>>>(R,t,pcb);
    k_featp2n<<<512,256>>>(z);
    cudaEventRecord(e3, 0);
    cudaStreamWaitEvent(s1, e3, 0);
    k_gemm1<<<dim3(64,2),256,0,s1>>>(W1,b1);
    k_ln1<<<512,256,0,s1>>>(ln1g,ln1b);
    k_out<<<512,256,0,s1>>>(x,W2,b2,lng,lnb,out);
    cudaStreamWaitEvent(0, e5, 0);           // g_act z-channels must be ready
    k_conv_cp<<<2048,256,CONV_SMEM>>>(cpb, out + 131072);

    // ---- join
    cudaEventRecord(e4, s1);
    cudaStreamWaitEvent(0, e4, 0);
}